// round 14
// baseline (speedup 1.0000x reference)
#include <cuda_runtime.h>
#include <mma.h>
#include <math.h>
#include <cstdint>
#include <stdint.h>

using namespace nvcuda;

#define Bn 2
#define Sn 2048
#define Dn 768
#define Hn 12
#define DHn 64
#define Fn 3072
#define Ln 2
#define BSn (Bn*Sn)
#define BHn (Bn*Hn)
#define NTILES 16              // Sn / 128 score column tiles
#define THREADS 512

// ---------------- scratch ----------------
__device__ float g_h  [BSn*Dn];     // full-precision residual stream
__device__ float g_hr [BSn*Dn];     // tf32-rounded copy for GEMM A operands
__device__ float g_qh [BSn*Dn];
__device__ float g_kh [BSn*Dn];
__device__ float g_vh [BSn*Dn];
__device__ float g_o  [BSn*Dn];
__device__ float g_t  [BSn*Dn];
__device__ float g_ff [BSn*Fn];
__device__ float g_ssum[BHn*Sn*NTILES];
// tf32-rounded weight copies: Wq,Wk,Wv,Wo (L*D*D each), W1,W2 (L*D*F each)
#define WDD (Ln*Dn*Dn)
#define WDF (Ln*Dn*Fn)
__device__ float g_wr [4*WDD + 2*WDF];

__device__ __forceinline__ float rnd_tf32(float x) { return wmma::__float_to_tf32(x); }

// ---------------- cp.async helpers ----------------
__device__ __forceinline__ void cp_async16(uint32_t saddr, const void* gaddr) {
    asm volatile("cp.async.cg.shared.global [%0], [%1], 16;\n" :: "r"(saddr), "l"(gaddr));
}
#define CP_COMMIT() asm volatile("cp.async.commit_group;\n" ::)
#define CP_WAIT1()  asm volatile("cp.async.wait_group 1;\n" ::)
#define CP_WAIT0()  asm volatile("cp.async.wait_group 0;\n" ::)

// ---------------- fused weight rounding (all 6 weights, one launch) ----------------
__global__ void round_all_w(const float* __restrict__ Wq, const float* __restrict__ Wk,
                            const float* __restrict__ Wv, const float* __restrict__ Wo,
                            const float* __restrict__ W1, const float* __restrict__ W2,
                            float* __restrict__ dst)
{
    const long total4 = (4L*WDD + 2L*WDF) / 4;
    long i4 = (long)blockIdx.x * blockDim.x + threadIdx.x;
    if (i4 >= total4) return;
    long i = i4 * 4;
    const float* src; long off;
    if      (i <  (long)WDD)        { src = Wq; off = i; }
    else if (i < 2L*WDD)            { src = Wk; off = i - WDD; }
    else if (i < 3L*WDD)            { src = Wv; off = i - 2L*WDD; }
    else if (i < 4L*WDD)            { src = Wo; off = i - 3L*WDD; }
    else if (i < 4L*WDD + WDF)      { src = W1; off = i - 4L*WDD; }
    else                            { src = W2; off = i - 4L*WDD - WDF; }
    float4 v = *(const float4*)(src + off);
    v.x = rnd_tf32(v.x); v.y = rnd_tf32(v.y); v.z = rnd_tf32(v.z); v.w = rnd_tf32(v.w);
    *(float4*)(dst + i) = v;
}

// ---------------- embedding + sinusoidal PE ----------------
__global__ void embed_kernel(const int* __restrict__ x, const float* __restrict__ emb,
                             float* __restrict__ h, float* __restrict__ hr)
{
    int row = blockIdx.x;
    int s   = row % Sn;
    long tok = x[row];
    const float* er = emb + tok * (long)Dn;
    float* hp = h + (long)row * Dn;
    float* hq = hr + (long)row * Dn;
    const float c = -logf(10000.0f) / (float)Dn;
    for (int j = threadIdx.x; j < Dn; j += blockDim.x) {
        float div = expf((float)(j & ~1) * c);
        float ang = (float)s * div;
        float pe = (j & 1) ? cosf(ang) : sinf(ang);
        float v = er[j] + pe;
        hp[j] = v;
        hq[j] = rnd_tf32(v);
    }
}

// ---------------- pipelined TF32 tensor-core GEMM (512 threads, 16 warps) ----------------
// Conversion-free mainloop (all operands pre-rounded to tf32-exact fp32).
// Warp tiles 32x32 (BN=128) or 16x32 (BN=64): small acc footprint -> regs<=64
// -> 2 CTAs x 512 threads = 32 warps/SM for latency hiding.
// MODE: 0 plain, 1 heads (QKV -> [b,h,s,d]), 2 merge (AV -> [b,s,D])
// MULTI: z selects {B0,B1,B2}.
// STATS: scores epilogue -> writes exp(s) to C + per-(row,tile) sumexp.
// SMAX:  A holds exp(s); MMA consumes raw E (scale hoisted to epilogue);
//        transform only writes final probs (E*sc) to gmem.
template<int BM, int BN, bool NT, int MODE, bool MULTI, bool STATS, bool SMAX>
__global__ __launch_bounds__(THREADS, 2)
void gemm_tc(const float* __restrict__ A,
             const float* B0, const float* B1, const float* B2,
             const float* bias0, const float* bias1, const float* bias2,
             float* C0, float* C1, float* C2,
             int M, int N, int K, int lda, int ldb, int ldc,
             long sA, long sB, long sC, float alpha, int relu, int rndout,
             float* st_sum)
{
    constexpr int BK = 32;
    constexpr int STAGES = 3;
    constexpr int LDA_S = BK + 4;
    constexpr int LDB_S = NT ? (BK + 4) : (BN + 4);
    constexpr int BROWS = NT ? BN : BK;
    constexpr int LDC_S = BN + 4;
    constexpr int WARPS_N = BN / 32;            // 4 or 2
    constexpr int WARPS_M = 16 / WARPS_N;       // 4 or 8
    constexpr int WM = BM / WARPS_M;            // 32 or 16
    constexpr int FM = WM / 16;                 // 2 or 1
    constexpr int FN = 2;                       // 32 cols per warp

    extern __shared__ char smem_raw[];
    float* As = (float*)smem_raw;                       // [STAGES][BM][LDA_S]
    float* Bs = As + STAGES * BM * LDA_S;               // [STAGES][BROWS][LDB_S]
    float* sm_scale = Bs + STAGES * BROWS * LDB_S;      // [BM] (SMAX only)
    float* Cs = (float*)smem_raw;                       // epilogue alias

    const int z = blockIdx.z;
    const float* Bm; const float* bias; float* C;
    if (MULTI) {
        Bm   = (z == 0) ? B0 : ((z == 1) ? B1 : B2);
        bias = (z == 0) ? bias0 : ((z == 1) ? bias1 : bias2);
        C    = (z == 0) ? C0 : ((z == 1) ? C1 : C2);
    } else {
        Bm   = B0 + z * sB;
        bias = bias0;
        C    = C0 + z * sC;
        A   += z * sA;
    }

    const int bm = blockIdx.y * BM;
    const int bn = blockIdx.x * BN;
    const int tid = threadIdx.x;
    const int warp = tid >> 5;
    const int lane = tid & 31;
    const int wm = (warp % WARPS_M) * WM;
    const int wn = (warp / WARPS_M) * 32;

    if (SMAX) {
        // per-row prob scale = 1 / sum_t tile_sums
        if (tid < BM) {
            const float* ps = st_sum + ((long)z * Sn + bm + tid) * NTILES;
            float S = 0.f;
#pragma unroll
            for (int t = 0; t < NTILES; t++) S += ps[t];
            sm_scale[tid] = 1.f / S;
        }
    }

    const uint32_t sAs = (uint32_t)__cvta_generic_to_shared(As);
    const uint32_t sBs = (uint32_t)__cvta_generic_to_shared(Bs);

    // strength-reduced global pointers (advance per k-iter); 512 threads
    const int a_row0 = tid >> 3;            // 0..63
    const int a_kv   = (tid & 7) * 4;
    const float* pA = A + (long)(bm + a_row0) * lda + a_kv;
    const long stepA = 64L * lda;
    constexpr int RPB = THREADS / (BN / 4); // !NT: B rows per pass (16 or 32)
    const int b_row0 = tid / (BN / 4);
    const int b_nv   = (tid % (BN / 4)) * 4;
    const int n0     = tid >> 3;            // NT path, 0..63
    const float* pB;
    long stepB, advB;
    if (!NT) { pB = Bm + (long)b_row0 * ldb + bn + b_nv; stepB = (long)RPB * ldb; advB = (long)BK * ldb; }
    else     { pB = Bm + (long)(bn + n0) * ldb + a_kv;   stepB = 64L * ldb;       advB = BK; }

    wmma::fragment<wmma::accumulator, 16, 16, 8, float> acc[FM][FN];
#pragma unroll
    for (int i = 0; i < FM; i++)
#pragma unroll
        for (int j = 0; j < FN; j++) wmma::fill_fragment(acc[i][j], 0.0f);

    const int kIters = K / BK;

    auto load_stage = [&](int st, int ki) {
        if (ki < kIters) {
#pragma unroll
            for (int p = 0; p < BM / 64; p++)
                cp_async16(sAs + ((st * BM + a_row0 + p * 64) * LDA_S + a_kv) * 4,
                           pA + p * stepA);
            if (!NT) {
#pragma unroll
                for (int p = 0; p < BK / RPB; p++)
                    cp_async16(sBs + ((st * BROWS + b_row0 + p * RPB) * LDB_S + b_nv) * 4,
                               pB + p * stepB);
            } else {
#pragma unroll
                for (int p = 0; p < BN / 64; p++)
                    cp_async16(sBs + ((st * BROWS + n0 + p * 64) * LDB_S + a_kv) * 4,
                               pB + p * stepB);
            }
        }
        pA += BK;
        pB += advB;
    };

    for (int s = 0; s < STAGES - 1; s++) { load_stage(s, s); CP_COMMIT(); }

    for (int ki = 0; ki < kIters; ki++) {
        CP_WAIT1();
        __syncthreads();
        load_stage((ki + STAGES - 1) % STAGES, ki + STAGES - 1);
        CP_COMMIT();

        const int st = ki % STAGES;
        float* Ast = As + st * BM * LDA_S;
        const float* Bst = Bs + st * BROWS * LDB_S;

        if (SMAX) {
            // write final probs (E * sc) to gmem; smem keeps raw E for the MMA.
            const int k0 = ki * BK;
            float* Awb = const_cast<float*>(A);
            constexpr int NVA = BM * BK / 4;
#pragma unroll
            for (int e = tid; e < NVA; e += THREADS) {
                int m  = e >> 3;
                int kv = (e & 7) * 4;
                float sc = sm_scale[m];
                float4 s4 = *(float4*)&Ast[m * LDA_S + kv];
                *(float4*)&Awb[(long)(bm + m) * lda + k0 + kv] =
                    make_float4(s4.x * sc, s4.y * sc, s4.z * sc, s4.w * sc);
            }
        }

#pragma unroll
        for (int kf = 0; kf < BK / 8; kf++) {
            wmma::fragment<wmma::matrix_a, 16, 16, 8, wmma::precision::tf32, wmma::row_major> af[FM];
#pragma unroll
            for (int i = 0; i < FM; i++)
                wmma::load_matrix_sync(af[i], Ast + (wm + i * 16) * LDA_S + kf * 8, LDA_S);
            if (!NT) {
                wmma::fragment<wmma::matrix_b, 16, 16, 8, wmma::precision::tf32, wmma::row_major> bf[FN];
#pragma unroll
                for (int j = 0; j < FN; j++)
                    wmma::load_matrix_sync(bf[j], Bst + (kf * 8) * LDB_S + wn + j * 16, LDB_S);
#pragma unroll
                for (int i = 0; i < FM; i++)
#pragma unroll
                    for (int j = 0; j < FN; j++)
                        wmma::mma_sync(acc[i][j], af[i], bf[j], acc[i][j]);
            } else {
                wmma::fragment<wmma::matrix_b, 16, 16, 8, wmma::precision::tf32, wmma::col_major> bf[FN];
#pragma unroll
                for (int j = 0; j < FN; j++)
                    wmma::load_matrix_sync(bf[j], Bst + (wn + j * 16) * LDB_S + kf * 8, LDB_S);
#pragma unroll
                for (int i = 0; i < FM; i++)
#pragma unroll
                    for (int j = 0; j < FN; j++)
                        wmma::mma_sync(acc[i][j], af[i], bf[j], acc[i][j]);
            }
        }
    }

    CP_WAIT0();
    __syncthreads();

#pragma unroll
    for (int i = 0; i < FM; i++)
#pragma unroll
        for (int j = 0; j < FN; j++)
            wmma::store_matrix_sync(Cs + (wm + i * 16) * LDC_S + wn + j * 16,
                                    acc[i][j], LDC_S, wmma::mem_row_major);
    __syncthreads();

    constexpr int NVC = BM * BN / 4;
    if (STATS) {
        // scores epilogue: write exp(s) + per-(row,tile) sumexp (no max shift)
#pragma unroll
        for (int p = 0; p < NVC / THREADS; p++) {
            int e  = tid + p * THREADS;
            int m  = e / (BN / 4);
            int nv = (e % (BN / 4)) * 4;
            float4 v = *(const float4*)&Cs[m * LDC_S + nv];
            float ex = __expf(v.x * alpha), ey = __expf(v.y * alpha);
            float ez = __expf(v.z * alpha), ew = __expf(v.w * alpha);
            *(float4*)&C[(long)(bm + m) * ldc + bn + nv] = make_float4(ex, ey, ez, ew);
            float lsum = ex + ey + ez + ew;
#pragma unroll
            for (int o = 16; o > 0; o >>= 1)
                lsum += __shfl_xor_sync(0xffffffffu, lsum, o);
            if (lane == 0) {
                long idx = ((long)z * Sn + bm + m) * NTILES + blockIdx.x;
                st_sum[idx] = lsum;
            }
        }
    } else {
#pragma unroll 4
        for (int e = tid; e < NVC; e += THREADS) {
            int m  = e / (BN / 4);
            int nv = (e % (BN / 4)) * 4;
            float4 v = *(const float4*)&Cs[m * LDC_S + nv];
            if (SMAX) {
                float sc = sm_scale[m];
                v.x *= sc; v.y *= sc; v.z *= sc; v.w *= sc;
            }
            if (alpha != 1.0f) { v.x *= alpha; v.y *= alpha; v.z *= alpha; v.w *= alpha; }
            if (bias) {
                int c = bn + nv;
                v.x += bias[c]; v.y += bias[c + 1]; v.z += bias[c + 2]; v.w += bias[c + 3];
            }
            if (relu) {
                v.x = fmaxf(v.x, 0.f); v.y = fmaxf(v.y, 0.f);
                v.z = fmaxf(v.z, 0.f); v.w = fmaxf(v.w, 0.f);
            }
            if (rndout) {
                v.x = rnd_tf32(v.x); v.y = rnd_tf32(v.y);
                v.z = rnd_tf32(v.z); v.w = rnd_tf32(v.w);
            }
            if (MODE == 0) {
                *(float4*)&C[(long)(bm + m) * ldc + bn + nv] = v;
            } else if (MODE == 1) {
                int r = bm + m, c = bn + nv;
                int b = r >> 11, s = r & (Sn - 1);
                int hh = c >> 6, d = c & 63;
                *(float4*)&C[((((long)b * Hn + hh) * Sn + s) << 6) + d] = v;
            } else {
                int b = z / Hn, hh = z % Hn;
                *(float4*)&C[((long)(b * Sn + bm + m)) * Dn + hh * DHn + bn + nv] = v;
            }
        }
    }
}

// ---------------- residual add + LayerNorm (full out + optional rounded copy) ----------------
__global__ void add_ln_kernel(const float* __restrict__ x, const float* __restrict__ d,
                              const float* __restrict__ g, const float* __restrict__ bb,
                              float* __restrict__ outf, float* __restrict__ outr)
{
    int row = blockIdx.x;
    int t = threadIdx.x;
    __shared__ float red[256];
    float v[3];
    float s = 0.f;
#pragma unroll
    for (int i = 0; i < 3; i++) {
        int c = t + i*256;
        v[i] = x[(long)row*Dn + c] + d[(long)row*Dn + c];
        s += v[i];
    }
    red[t] = s; __syncthreads();
    for (int o = 128; o > 0; o >>= 1) { if (t < o) red[t] += red[t+o]; __syncthreads(); }
    float mu = red[0] / (float)Dn;
    __syncthreads();
    float s2 = 0.f;
#pragma unroll
    for (int i = 0; i < 3; i++) { float dv = v[i] - mu; s2 += dv*dv; }
    red[t] = s2; __syncthreads();
    for (int o = 128; o > 0; o >>= 1) { if (t < o) red[t] += red[t+o]; __syncthreads(); }
    float inv = rsqrtf(red[0] / (float)Dn + 1e-5f);
    __syncthreads();
#pragma unroll
    for (int i = 0; i < 3; i++) {
        int c = t + i*256;
        float r = (v[i] - mu) * inv * g[c] + bb[c];
        outf[(long)row*Dn + c] = r;
        if (outr) outr[(long)row*Dn + c] = rnd_tf32(r);
    }
}

// ---------------- host side ----------------
#define SYM_PTR(sym) ([]{ void* p_; cudaGetSymbolAddress(&p_, sym); return (float*)p_; }())

#define SMEM_NN128 ((3*(128*36 + 32*132))*4)            // 105984  (BN=128 dense)
#define SMEM_NT128 ((3*(128*36 + 128*36))*4)            // 110592  (scores)
#define SMEM_AV    ((3*(128*36 + 32*68) + 128)*4)       // 81920   (AV BM=128, incl. scale)
#define SMEM_NN64  ((3*(128*36 + 32*68))*4)             // 81408   (BN=64 dense)

extern "C" void kernel_launch(void* const* d_in, const int* in_sizes, int n_in,
                              void* d_out, int out_size)
{
    const int*   x    = (const int*)  d_in[0];
    const float* emb  = (const float*)d_in[1];
    const float* Wq   = (const float*)d_in[2];
    const float* bq   = (const float*)d_in[3];
    const float* Wk   = (const float*)d_in[4];
    const float* bk   = (const float*)d_in[5];
    const float* Wv   = (const float*)d_in[6];
    const float* bv   = (const float*)d_in[7];
    const float* Wo   = (const float*)d_in[8];
    const float* bo   = (const float*)d_in[9];
    const float* ln1g = (const float*)d_in[10];
    const float* ln1b = (const float*)d_in[11];
    const float* ln2g = (const float*)d_in[12];
    const float* ln2b = (const float*)d_in[13];
    const float* W1   = (const float*)d_in[14];
    const float* b1   = (const float*)d_in[15];
    const float* W2   = (const float*)d_in[16];
    const float* b2   = (const float*)d_in[17];

    float* out = (float*)d_out;

    float* h    = SYM_PTR(g_h);
    float* hr   = SYM_PTR(g_hr);
    float* qh   = SYM_PTR(g_qh);
    float* kh   = SYM_PTR(g_kh);
    float* vh   = SYM_PTR(g_vh);
    float* o    = SYM_PTR(g_o);
    float* t    = SYM_PTR(g_t);
    float* ff   = SYM_PTR(g_ff);
    float* ssum = SYM_PTR(g_ssum);
    float* wr   = SYM_PTR(g_wr);

    float* Wq_r = wr;
    float* Wk_r = Wq_r + WDD;
    float* Wv_r = Wk_r + WDD;
    float* Wo_r = Wv_r + WDD;
    float* W1_r = Wo_r + WDD;
    float* W2_r = W1_r + WDF;

    cudaFuncSetAttribute(gemm_tc<128,128,false,1,true ,false,false>, cudaFuncAttributeMaxDynamicSharedMemorySize, SMEM_NN128);
    cudaFuncSetAttribute(gemm_tc<128,128,false,0,false,false,false>, cudaFuncAttributeMaxDynamicSharedMemorySize, SMEM_NN128);
    cudaFuncSetAttribute(gemm_tc<128,128,true ,0,false,true ,false>, cudaFuncAttributeMaxDynamicSharedMemorySize, SMEM_NT128);
    cudaFuncSetAttribute(gemm_tc<128,64 ,false,2,false,false,true >, cudaFuncAttributeMaxDynamicSharedMemorySize, SMEM_AV);
    cudaFuncSetAttribute(gemm_tc<128,64 ,false,0,false,false,false>, cudaFuncAttributeMaxDynamicSharedMemorySize, SMEM_NN64);

    {
        long total4 = (4L*WDD + 2L*WDF) / 4;
        round_all_w<<<(int)((total4 + 255)/256), 256>>>(Wq, Wk, Wv, Wo, W1, W2, wr);
    }
    embed_kernel<<<BSn, 256>>>(x, emb, h, hr);

    for (int l = 0; l < Ln; l++) {
        const float* Wq_l = Wq_r + (long)l*Dn*Dn; const float* bq_l = bq + (long)l*Dn;
        const float* Wk_l = Wk_r + (long)l*Dn*Dn; const float* bk_l = bk + (long)l*Dn;
        const float* Wv_l = Wv_r + (long)l*Dn*Dn; const float* bv_l = bv + (long)l*Dn;
        const float* Wo_l = Wo_r + (long)l*Dn*Dn; const float* bo_l = bo + (long)l*Dn;
        const float* W1_l = W1_r + (long)l*Dn*Fn; const float* b1_l = b1 + (long)l*Fn;
        const float* W2_l = W2_r + (long)l*Fn*Dn; const float* b2_l = b2 + (long)l*Dn;
        float* maps = out + (long)BSn*Dn + (long)l*Bn*Hn*Sn*Sn;

        // QKV fused -> head layout (outputs tf32-rounded; A = rounded hr)
        {
            dim3 grid(Dn/128, BSn/128, 3);
            gemm_tc<128,128,false,1,true,false,false><<<grid,THREADS,SMEM_NN128>>>(
                hr, Wq_l, Wk_l, Wv_l, bq_l, bk_l, bv_l, qh, kh, vh,
                BSn, Dn, Dn, Dn, Dn, 0, 0,0,0, 1.f, 0, 1,
                nullptr);
        }
        // scores = Q K^T / 8 -> maps holds exp(s) + per-(row,tile) sums
        {
            dim3 grid(Sn/128, Sn/128, BHn);
            gemm_tc<128,128,true,0,false,true,false><<<grid,THREADS,SMEM_NT128>>>(
                qh, kh, nullptr, nullptr, nullptr, nullptr, nullptr,
                maps, nullptr, nullptr,
                Sn, Sn, DHn, DHn, DHn, Sn,
                (long)Sn*DHn, (long)Sn*DHn, (long)Sn*Sn, 0.125f, 0, 0,
                ssum);
        }
        // O = (E @ V) * sc  (scale hoisted to epilogue; final probs written to maps)
        {
            dim3 grid(1, Sn/128, BHn);
            gemm_tc<128,64,false,2,false,false,true><<<grid,THREADS,SMEM_AV>>>(
                maps, vh, nullptr, nullptr, nullptr, nullptr, nullptr,
                o, nullptr, nullptr,
                Sn, DHn, Sn, Sn, DHn, 0,
                (long)Sn*Sn, (long)Sn*DHn, 0, 1.f, 0, 1,
                ssum);
        }
        // attn_out = o @ Wo + bo (BN=64 -> 384 CTAs)
        {
            dim3 grid(Dn/64, BSn/128, 1);
            gemm_tc<128,64,false,0,false,false,false><<<grid,THREADS,SMEM_NN64>>>(
                o, Wo_l, nullptr, nullptr, bo_l, nullptr, nullptr,
                t, nullptr, nullptr,
                BSn, Dn, Dn, Dn, Dn, Dn, 0,0,0, 1.f, 0, 0,
                nullptr);
        }
        add_ln_kernel<<<BSn,256>>>(h, t, ln1g + (long)l*Dn, ln1b + (long)l*Dn, h, hr);
        // ff = relu(hr @ W1 + b1)
        {
            dim3 grid(Fn/128, BSn/128, 1);
            gemm_tc<128,128,false,0,false,false,false><<<grid,THREADS,SMEM_NN128>>>(
                hr, W1_l, nullptr, nullptr, b1_l, nullptr, nullptr,
                ff, nullptr, nullptr,
                BSn, Fn, Dn, Dn, Fn, Fn, 0,0,0, 1.f, 1, 1,
                nullptr);
        }
        // t = ff @ W2 + b2 (BN=64 -> 384 CTAs)
        {
            dim3 grid(Dn/64, BSn/128, 1);
            gemm_tc<128,64,false,0,false,false,false><<<grid,THREADS,SMEM_NN64>>>(
                ff, W2_l, nullptr, nullptr, b2_l, nullptr, nullptr,
                t, nullptr, nullptr,
                BSn, Dn, Fn, Fn, Dn, Dn, 0,0,0, 1.f, 0, 0,
                nullptr);
        }
        if (l == Ln-1)
            add_ln_kernel<<<BSn,256>>>(h, t, ln2g + (long)l*Dn, ln2b + (long)l*Dn, out, nullptr);
        else
            add_ln_kernel<<<BSn,256>>>(h, t, ln2g + (long)l*Dn, ln2b + (long)l*Dn, h, hr);
    }
}

// round 15
// speedup vs baseline: 1.1674x; 1.1674x over previous
#include <cuda_runtime.h>
#include <mma.h>
#include <math.h>
#include <cstdint>
#include <stdint.h>

using namespace nvcuda;

#define Bn 2
#define Sn 2048
#define Dn 768
#define Hn 12
#define DHn 64
#define Fn 3072
#define Ln 2
#define BSn (Bn*Sn)
#define BHn (Bn*Hn)
#define NTILES 16              // Sn / 128 score column tiles

// ---------------- scratch ----------------
__device__ float g_h  [BSn*Dn];     // full-precision residual stream
__device__ float g_hr [BSn*Dn];     // tf32-rounded copy for GEMM A operands
__device__ float g_qh [BSn*Dn];
__device__ float g_kh [BSn*Dn];
__device__ float g_vh [BSn*Dn];
__device__ float g_o  [BSn*Dn];
__device__ float g_t  [BSn*Dn];
__device__ float g_ff [BSn*Fn];
__device__ float g_ssum[BHn*Sn*NTILES];
// tf32-rounded weight copies: Wq,Wk,Wv,Wo (L*D*D each), W1,W2 (L*D*F each)
#define WDD (Ln*Dn*Dn)
#define WDF (Ln*Dn*Fn)
__device__ float g_wr [4*WDD + 2*WDF];

__device__ __forceinline__ float rnd_tf32(float x) { return wmma::__float_to_tf32(x); }

// ---------------- cp.async helpers ----------------
__device__ __forceinline__ void cp_async16(uint32_t saddr, const void* gaddr) {
    asm volatile("cp.async.cg.shared.global [%0], [%1], 16;\n" :: "r"(saddr), "l"(gaddr));
}
#define CP_COMMIT() asm volatile("cp.async.commit_group;\n" ::)
#define CP_WAIT1()  asm volatile("cp.async.wait_group 1;\n" ::)
#define CP_WAIT0()  asm volatile("cp.async.wait_group 0;\n" ::)

// ---------------- fused weight rounding (all 6 weights, one launch) ----------------
__global__ void round_all_w(const float* __restrict__ Wq, const float* __restrict__ Wk,
                            const float* __restrict__ Wv, const float* __restrict__ Wo,
                            const float* __restrict__ W1, const float* __restrict__ W2,
                            float* __restrict__ dst)
{
    const long total4 = (4L*WDD + 2L*WDF) / 4;
    long i4 = (long)blockIdx.x * blockDim.x + threadIdx.x;
    if (i4 >= total4) return;
    long i = i4 * 4;
    const float* src; long off;
    if      (i <  (long)WDD)        { src = Wq; off = i; }
    else if (i < 2L*WDD)            { src = Wk; off = i - WDD; }
    else if (i < 3L*WDD)            { src = Wv; off = i - 2L*WDD; }
    else if (i < 4L*WDD)            { src = Wo; off = i - 3L*WDD; }
    else if (i < 4L*WDD + WDF)      { src = W1; off = i - 4L*WDD; }
    else                            { src = W2; off = i - 4L*WDD - WDF; }
    float4 v = *(const float4*)(src + off);
    v.x = rnd_tf32(v.x); v.y = rnd_tf32(v.y); v.z = rnd_tf32(v.z); v.w = rnd_tf32(v.w);
    *(float4*)(dst + i) = v;
}

// ---------------- embedding + sinusoidal PE ----------------
__global__ void embed_kernel(const int* __restrict__ x, const float* __restrict__ emb,
                             float* __restrict__ h, float* __restrict__ hr)
{
    int row = blockIdx.x;
    int s   = row % Sn;
    long tok = x[row];
    const float* er = emb + tok * (long)Dn;
    float* hp = h + (long)row * Dn;
    float* hq = hr + (long)row * Dn;
    const float c = -logf(10000.0f) / (float)Dn;
    for (int j = threadIdx.x; j < Dn; j += blockDim.x) {
        float div = expf((float)(j & ~1) * c);
        float ang = (float)s * div;
        float pe = (j & 1) ? cosf(ang) : sinf(ang);
        float v = er[j] + pe;
        hp[j] = v;
        hq[j] = rnd_tf32(v);
    }
}

// ============ specialized scores kernel: S = Q K^T (K=64, single-shot) ============
// Per CTA: 128x128 score tile of one (b,h). Q/K tiles loaded ONCE (no pipeline).
// Epilogue: write exp(s/8) to maps + per-(row, tile) sumexp (no max shift:
// |s| <= ~5 here, exp and row sums are far from fp32 limits).
#define LDQK 68
#define LDSC 132
#define SMEM_SC ((2*128*LDQK)*4)    // 69632 bytes; epilogue alias needs 128*132*4=67584

__global__ __launch_bounds__(256, 2)
void scores_kernel(const float* __restrict__ qh, const float* __restrict__ kh,
                   float* __restrict__ maps, float* __restrict__ st_sum)
{
    extern __shared__ float sm[];
    float* Qs = sm;                 // [128][LDQK]
    float* Ks = Qs + 128*LDQK;      // [128][LDQK]
    float* Cs = sm;                 // epilogue alias [128][LDSC]

    const int z  = blockIdx.z;
    const int bm = blockIdx.y * 128;
    const int bn = blockIdx.x * 128;
    const int tid = threadIdx.x;
    const int warp = tid >> 5;
    const int lane = tid & 31;
    const int wm = (warp & 3) * 32;     // 4 warps over M
    const int wn = (warp >> 2) * 64;    // 2 warps over N

    const float* Qg = qh + ((long)z * Sn + bm) * DHn;
    const float* Kg = kh + ((long)z * Sn + bn) * DHn;
    const uint32_t sQ = (uint32_t)__cvta_generic_to_shared(Qs);
    const uint32_t sK = (uint32_t)__cvta_generic_to_shared(Ks);

    // single-shot load of both 128x64 tiles
#pragma unroll
    for (int p = 0; p < 8; p++) {
        int e = tid + p * 256;
        int r = e >> 4, c4 = (e & 15) * 4;
        cp_async16(sQ + (r * LDQK + c4) * 4, Qg + (long)r * DHn + c4);
        cp_async16(sK + (r * LDQK + c4) * 4, Kg + (long)r * DHn + c4);
    }
    CP_COMMIT(); CP_WAIT0();
    __syncthreads();

    wmma::fragment<wmma::accumulator, 16, 16, 8, float> acc[2][4];
#pragma unroll
    for (int i = 0; i < 2; i++)
#pragma unroll
        for (int j = 0; j < 4; j++) wmma::fill_fragment(acc[i][j], 0.0f);

#pragma unroll
    for (int kf = 0; kf < 8; kf++) {
        wmma::fragment<wmma::matrix_a, 16, 16, 8, wmma::precision::tf32, wmma::row_major> af[2];
#pragma unroll
        for (int i = 0; i < 2; i++)
            wmma::load_matrix_sync(af[i], Qs + (wm + i * 16) * LDQK + kf * 8, LDQK);
        wmma::fragment<wmma::matrix_b, 16, 16, 8, wmma::precision::tf32, wmma::col_major> bf[4];
#pragma unroll
        for (int j = 0; j < 4; j++)
            wmma::load_matrix_sync(bf[j], Ks + (wn + j * 16) * LDQK + kf * 8, LDQK);
#pragma unroll
        for (int i = 0; i < 2; i++)
#pragma unroll
            for (int j = 0; j < 4; j++)
                wmma::mma_sync(acc[i][j], af[i], bf[j], acc[i][j]);
    }

    __syncthreads();   // tiles consumed; reuse smem for epilogue
#pragma unroll
    for (int i = 0; i < 2; i++)
#pragma unroll
        for (int j = 0; j < 4; j++)
            wmma::store_matrix_sync(Cs + (wm + i * 16) * LDSC + wn + j * 16,
                                    acc[i][j], LDSC, wmma::mem_row_major);
    __syncthreads();

    float* C = maps + (long)z * Sn * Sn;
#pragma unroll
    for (int p = 0; p < 16; p++) {
        int e  = tid + p * 256;
        int m  = e >> 5;
        int nv = (e & 31) * 4;
        float4 v = *(const float4*)&Cs[m * LDSC + nv];
        float ex = __expf(v.x * 0.125f), ey = __expf(v.y * 0.125f);
        float ez = __expf(v.z * 0.125f), ew = __expf(v.w * 0.125f);
        *(float4*)&C[(long)(bm + m) * Sn + bn + nv] = make_float4(ex, ey, ez, ew);
        float lsum = ex + ey + ez + ew;
#pragma unroll
        for (int o = 16; o > 0; o >>= 1)
            lsum += __shfl_xor_sync(0xffffffffu, lsum, o);
        if (lane == 0)
            st_sum[((long)z * Sn + bm + m) * NTILES + blockIdx.x] = lsum;
    }
}

// ---------------- pipelined TF32 tensor-core GEMM (R13 config: 256 thr, 8 warps) ----------------
// Conversion-free mainloop (all operands pre-rounded to tf32-exact fp32).
// MODE: 0 plain, 1 heads (QKV -> [b,h,s,d]), 2 merge (AV -> [b,s,D])
// MULTI: z selects {B0,B1,B2}.
// SMAX:  A holds exp(s); MMA consumes raw E (scale hoisted to epilogue);
//        transform only writes final probs (E*sc) to gmem.
template<int BM, int BN, int MODE, bool MULTI, bool SMAX>
__global__ __launch_bounds__(256, 2)
void gemm_tc(const float* __restrict__ A,
             const float* B0, const float* B1, const float* B2,
             const float* bias0, const float* bias1, const float* bias2,
             float* C0, float* C1, float* C2,
             int M, int N, int K, int lda, int ldb, int ldc,
             long sA, long sB, long sC, int relu, int rndout,
             float* st_sum)
{
    constexpr int BK = 32;
    constexpr int STAGES = 3;
    constexpr int LDA_S = BK + 4;
    constexpr int LDB_S = BN + 4;
    constexpr int LDC_S = BN + 4;
    constexpr int WARPS_M = 4, WARPS_N = 2;
    constexpr int WM = BM / WARPS_M;
    constexpr int WN = BN / WARPS_N;
    constexpr int FM = WM / 16;
    constexpr int FN = WN / 16;

    extern __shared__ char smem_raw[];
    float* As = (float*)smem_raw;                       // [STAGES][BM][LDA_S]
    float* Bs = As + STAGES * BM * LDA_S;               // [STAGES][BK][LDB_S]
    float* sm_scale = Bs + STAGES * BK * LDB_S;         // [BM] (SMAX only)
    float* Cs = (float*)smem_raw;                       // epilogue alias

    const int z = blockIdx.z;
    const float* Bm; const float* bias; float* C;
    if (MULTI) {
        Bm   = (z == 0) ? B0 : ((z == 1) ? B1 : B2);
        bias = (z == 0) ? bias0 : ((z == 1) ? bias1 : bias2);
        C    = (z == 0) ? C0 : ((z == 1) ? C1 : C2);
    } else {
        Bm   = B0 + z * sB;
        bias = bias0;
        C    = C0 + z * sC;
        A   += z * sA;
    }

    const int bm = blockIdx.y * BM;
    const int bn = blockIdx.x * BN;
    const int tid = threadIdx.x;
    const int warp = tid >> 5;
    const int wm = (warp % WARPS_M) * WM;
    const int wn = (warp / WARPS_M) * WN;

    if (SMAX) {
        // per-row prob scale = 1 / sum_t tile_sums
        if (tid < BM) {
            const float* ps = st_sum + ((long)z * Sn + bm + tid) * NTILES;
            float S = 0.f;
#pragma unroll
            for (int t = 0; t < NTILES; t++) S += ps[t];
            sm_scale[tid] = 1.f / S;
        }
    }

    const uint32_t sAs = (uint32_t)__cvta_generic_to_shared(As);
    const uint32_t sBs = (uint32_t)__cvta_generic_to_shared(Bs);

    // strength-reduced global pointers (advance per k-iter)
    const int a_row0 = tid >> 3;
    const int a_kv   = (tid & 7) * 4;
    const float* pA = A + (long)(bm + a_row0) * lda + a_kv;
    const long stepA = 32L * lda;
    constexpr int RPB = 256 / (BN / 4);
    const int b_row0 = tid / (BN / 4);
    const int b_nv   = (tid % (BN / 4)) * 4;
    const float* pB = Bm + (long)b_row0 * ldb + bn + b_nv;
    const long stepB = (long)RPB * ldb;
    const long advB  = (long)BK * ldb;

    wmma::fragment<wmma::accumulator, 16, 16, 8, float> acc[FM][FN];
#pragma unroll
    for (int i = 0; i < FM; i++)
#pragma unroll
        for (int j = 0; j < FN; j++) wmma::fill_fragment(acc[i][j], 0.0f);

    const int kIters = K / BK;

    auto load_stage = [&](int st, int ki) {
        if (ki < kIters) {
#pragma unroll
            for (int p = 0; p < BM / 32; p++)
                cp_async16(sAs + ((st * BM + a_row0 + p * 32) * LDA_S + a_kv) * 4,
                           pA + p * stepA);
#pragma unroll
            for (int p = 0; p < BK / RPB; p++)
                cp_async16(sBs + ((st * BK + b_row0 + p * RPB) * LDB_S + b_nv) * 4,
                           pB + p * stepB);
        }
        pA += BK;
        pB += advB;
    };

    for (int s = 0; s < STAGES - 1; s++) { load_stage(s, s); CP_COMMIT(); }

    for (int ki = 0; ki < kIters; ki++) {
        CP_WAIT1();
        __syncthreads();
        load_stage((ki + STAGES - 1) % STAGES, ki + STAGES - 1);
        CP_COMMIT();

        const int st = ki % STAGES;
        float* Ast = As + st * BM * LDA_S;
        const float* Bst = Bs + st * BK * LDB_S;

        if (SMAX) {
            // write final probs (E * sc) to gmem; smem keeps raw E for the MMA.
            const int k0 = ki * BK;
            float* Awb = const_cast<float*>(A);
            constexpr int NVA = BM * BK / 4;
#pragma unroll
            for (int e = tid; e < NVA; e += 256) {
                int m  = e >> 3;
                int kv = (e & 7) * 4;
                float sc = sm_scale[m];
                float4 s4 = *(float4*)&Ast[m * LDA_S + kv];
                *(float4*)&Awb[(long)(bm + m) * lda + k0 + kv] =
                    make_float4(s4.x * sc, s4.y * sc, s4.z * sc, s4.w * sc);
            }
        }

#pragma unroll
        for (int kf = 0; kf < BK / 8; kf++) {
            wmma::fragment<wmma::matrix_a, 16, 16, 8, wmma::precision::tf32, wmma::row_major> af[FM];
#pragma unroll
            for (int i = 0; i < FM; i++)
                wmma::load_matrix_sync(af[i], Ast + (wm + i * 16) * LDA_S + kf * 8, LDA_S);
            wmma::fragment<wmma::matrix_b, 16, 16, 8, wmma::precision::tf32, wmma::row_major> bf[FN];
#pragma unroll
            for (int j = 0; j < FN; j++)
                wmma::load_matrix_sync(bf[j], Bst + (kf * 8) * LDB_S + wn + j * 16, LDB_S);
#pragma unroll
            for (int i = 0; i < FM; i++)
#pragma unroll
                for (int j = 0; j < FN; j++)
                    wmma::mma_sync(acc[i][j], af[i], bf[j], acc[i][j]);
        }
    }

    CP_WAIT0();
    __syncthreads();

#pragma unroll
    for (int i = 0; i < FM; i++)
#pragma unroll
        for (int j = 0; j < FN; j++)
            wmma::store_matrix_sync(Cs + (wm + i * 16) * LDC_S + wn + j * 16,
                                    acc[i][j], LDC_S, wmma::mem_row_major);
    __syncthreads();

    constexpr int NVC = BM * BN / 4;
#pragma unroll 4
    for (int e = tid; e < NVC; e += 256) {
        int m  = e / (BN / 4);
        int nv = (e % (BN / 4)) * 4;
        float4 v = *(const float4*)&Cs[m * LDC_S + nv];
        if (SMAX) {
            float sc = sm_scale[m];
            v.x *= sc; v.y *= sc; v.z *= sc; v.w *= sc;
        }
        if (bias) {
            int c = bn + nv;
            v.x += bias[c]; v.y += bias[c + 1]; v.z += bias[c + 2]; v.w += bias[c + 3];
        }
        if (relu) {
            v.x = fmaxf(v.x, 0.f); v.y = fmaxf(v.y, 0.f);
            v.z = fmaxf(v.z, 0.f); v.w = fmaxf(v.w, 0.f);
        }
        if (rndout) {
            v.x = rnd_tf32(v.x); v.y = rnd_tf32(v.y);
            v.z = rnd_tf32(v.z); v.w = rnd_tf32(v.w);
        }
        if (MODE == 0) {
            *(float4*)&C[(long)(bm + m) * ldc + bn + nv] = v;
        } else if (MODE == 1) {
            int r = bm + m, c = bn + nv;
            int b = r >> 11, s = r & (Sn - 1);
            int hh = c >> 6, d = c & 63;
            *(float4*)&C[((((long)b * Hn + hh) * Sn + s) << 6) + d] = v;
        } else {
            int b = z / Hn, hh = z % Hn;
            *(float4*)&C[((long)(b * Sn + bm + m)) * Dn + hh * DHn + bn + nv] = v;
        }
    }
}

// ---------------- residual add + LayerNorm (full out + optional rounded copy) ----------------
__global__ void add_ln_kernel(const float* __restrict__ x, const float* __restrict__ d,
                              const float* __restrict__ g, const float* __restrict__ bb,
                              float* __restrict__ outf, float* __restrict__ outr)
{
    int row = blockIdx.x;
    int t = threadIdx.x;
    __shared__ float red[256];
    float v[3];
    float s = 0.f;
#pragma unroll
    for (int i = 0; i < 3; i++) {
        int c = t + i*256;
        v[i] = x[(long)row*Dn + c] + d[(long)row*Dn + c];
        s += v[i];
    }
    red[t] = s; __syncthreads();
    for (int o = 128; o > 0; o >>= 1) { if (t < o) red[t] += red[t+o]; __syncthreads(); }
    float mu = red[0] / (float)Dn;
    __syncthreads();
    float s2 = 0.f;
#pragma unroll
    for (int i = 0; i < 3; i++) { float dv = v[i] - mu; s2 += dv*dv; }
    red[t] = s2; __syncthreads();
    for (int o = 128; o > 0; o >>= 1) { if (t < o) red[t] += red[t+o]; __syncthreads(); }
    float inv = rsqrtf(red[0] / (float)Dn + 1e-5f);
    __syncthreads();
#pragma unroll
    for (int i = 0; i < 3; i++) {
        int c = t + i*256;
        float r = (v[i] - mu) * inv * g[c] + bb[c];
        outf[(long)row*Dn + c] = r;
        if (outr) outr[(long)row*Dn + c] = rnd_tf32(r);
    }
}

// ---------------- host side ----------------
#define SYM_PTR(sym) ([]{ void* p_; cudaGetSymbolAddress(&p_, sym); return (float*)p_; }())

#define SMEM_NN128 ((3*(128*36 + 32*132))*4)            // 105984  (BN=128 dense)
#define SMEM_AV    ((3*(128*36 + 32*68) + 128)*4)       // 81920   (AV BM=128, incl. scale)
#define SMEM_NN64  ((3*(128*36 + 32*68))*4)             // 81408   (BN=64 dense)

extern "C" void kernel_launch(void* const* d_in, const int* in_sizes, int n_in,
                              void* d_out, int out_size)
{
    const int*   x    = (const int*)  d_in[0];
    const float* emb  = (const float*)d_in[1];
    const float* Wq   = (const float*)d_in[2];
    const float* bq   = (const float*)d_in[3];
    const float* Wk   = (const float*)d_in[4];
    const float* bk   = (const float*)d_in[5];
    const float* Wv   = (const float*)d_in[6];
    const float* bv   = (const float*)d_in[7];
    const float* Wo   = (const float*)d_in[8];
    const float* bo   = (const float*)d_in[9];
    const float* ln1g = (const float*)d_in[10];
    const float* ln1b = (const float*)d_in[11];
    const float* ln2g = (const float*)d_in[12];
    const float* ln2b = (const float*)d_in[13];
    const float* W1   = (const float*)d_in[14];
    const float* b1   = (const float*)d_in[15];
    const float* W2   = (const float*)d_in[16];
    const float* b2   = (const float*)d_in[17];

    float* out = (float*)d_out;

    float* h    = SYM_PTR(g_h);
    float* hr   = SYM_PTR(g_hr);
    float* qh   = SYM_PTR(g_qh);
    float* kh   = SYM_PTR(g_kh);
    float* vh   = SYM_PTR(g_vh);
    float* o    = SYM_PTR(g_o);
    float* t    = SYM_PTR(g_t);
    float* ff   = SYM_PTR(g_ff);
    float* ssum = SYM_PTR(g_ssum);
    float* wr   = SYM_PTR(g_wr);

    float* Wq_r = wr;
    float* Wk_r = Wq_r + WDD;
    float* Wv_r = Wk_r + WDD;
    float* Wo_r = Wv_r + WDD;
    float* W1_r = Wo_r + WDD;
    float* W2_r = W1_r + WDF;

    cudaFuncSetAttribute(gemm_tc<128,128,1,true ,false>, cudaFuncAttributeMaxDynamicSharedMemorySize, SMEM_NN128);
    cudaFuncSetAttribute(gemm_tc<128,128,0,false,false>, cudaFuncAttributeMaxDynamicSharedMemorySize, SMEM_NN128);
    cudaFuncSetAttribute(gemm_tc<128,64 ,2,false,true >, cudaFuncAttributeMaxDynamicSharedMemorySize, SMEM_AV);
    cudaFuncSetAttribute(gemm_tc<128,64 ,0,false,false>, cudaFuncAttributeMaxDynamicSharedMemorySize, SMEM_NN64);
    cudaFuncSetAttribute(scores_kernel, cudaFuncAttributeMaxDynamicSharedMemorySize, SMEM_SC);

    {
        long total4 = (4L*WDD + 2L*WDF) / 4;
        round_all_w<<<(int)((total4 + 255)/256), 256>>>(Wq, Wk, Wv, Wo, W1, W2, wr);
    }
    embed_kernel<<<BSn, 256>>>(x, emb, h, hr);

    for (int l = 0; l < Ln; l++) {
        const float* Wq_l = Wq_r + (long)l*Dn*Dn; const float* bq_l = bq + (long)l*Dn;
        const float* Wk_l = Wk_r + (long)l*Dn*Dn; const float* bk_l = bk + (long)l*Dn;
        const float* Wv_l = Wv_r + (long)l*Dn*Dn; const float* bv_l = bv + (long)l*Dn;
        const float* Wo_l = Wo_r + (long)l*Dn*Dn; const float* bo_l = bo + (long)l*Dn;
        const float* W1_l = W1_r + (long)l*Dn*Fn; const float* b1_l = b1 + (long)l*Fn;
        const float* W2_l = W2_r + (long)l*Fn*Dn; const float* b2_l = b2 + (long)l*Dn;
        float* maps = out + (long)BSn*Dn + (long)l*Bn*Hn*Sn*Sn;

        // QKV fused -> head layout (outputs tf32-rounded; A = rounded hr)
        {
            dim3 grid(Dn/128, BSn/128, 3);
            gemm_tc<128,128,1,true,false><<<grid,256,SMEM_NN128>>>(
                hr, Wq_l, Wk_l, Wv_l, bq_l, bk_l, bv_l, qh, kh, vh,
                BSn, Dn, Dn, Dn, Dn, 0, 0,0,0, 0, 1,
                nullptr);
        }
        // scores: dedicated single-shot kernel (exp(s/8) to maps + tile sums)
        {
            dim3 grid(Sn/128, Sn/128, BHn);
            scores_kernel<<<grid,256,SMEM_SC>>>(qh, kh, maps, ssum);
        }
        // O = (E @ V) * sc  (scale hoisted to epilogue; final probs written to maps)
        {
            dim3 grid(1, Sn/128, BHn);
            gemm_tc<128,64,2,false,true><<<grid,256,SMEM_AV>>>(
                maps, vh, nullptr, nullptr, nullptr, nullptr, nullptr,
                o, nullptr, nullptr,
                Sn, DHn, Sn, Sn, DHn, 0,
                (long)Sn*Sn, (long)Sn*DHn, 0, 0, 1,
                ssum);
        }
        // attn_out = o @ Wo + bo (BN=64 -> 384 CTAs)
        {
            dim3 grid(Dn/64, BSn/128, 1);
            gemm_tc<128,64,0,false,false><<<grid,256,SMEM_NN64>>>(
                o, Wo_l, nullptr, nullptr, bo_l, nullptr, nullptr,
                t, nullptr, nullptr,
                BSn, Dn, Dn, Dn, Dn, Dn, 0,0,0, 0, 0,
                nullptr);
        }
        add_ln_kernel<<<BSn,256>>>(h, t, ln1g + (long)l*Dn, ln1b + (long)l*Dn, h, hr);
        // ff = relu(hr @ W1 + b1)
        {
            dim3 grid(Fn/128, BSn/128, 1);
            gemm_tc<128,128,0,false,false><<<grid,256,SMEM_NN128>>>(
                hr, W1_l, nullptr, nullptr, b1_l, nullptr, nullptr,
                ff, nullptr, nullptr,
                BSn, Fn, Dn, Dn, Fn, Fn, 0,0,0, 1, 1,
                nullptr);
        }
        // t = ff @ W2 + b2 (BN=64 -> 384 CTAs)
        {
            dim3 grid(Dn/64, BSn/128, 1);
            gemm_tc<128,64,0,false,false><<<grid,256,SMEM_NN64>>>(
                ff, W2_l, nullptr, nullptr, b2_l, nullptr, nullptr,
                t, nullptr, nullptr,
                BSn, Dn, Fn, Fn, Dn, Dn, 0,0,0, 0, 0,
                nullptr);
        }
        if (l == Ln-1)
            add_ln_kernel<<<BSn,256>>>(h, t, ln2g + (long)l*Dn, ln2b + (long)l*Dn, out, nullptr);
        else
            add_ln_kernel<<<BSn,256>>>(h, t, ln2g + (long)l*Dn, ln2b + (long)l*Dn, h, hr);
    }
}

// round 16
// speedup vs baseline: 1.1746x; 1.0062x over previous
#include <cuda_runtime.h>
#include <mma.h>
#include <math.h>
#include <cstdint>
#include <stdint.h>

using namespace nvcuda;

#define Bn 2
#define Sn 2048
#define Dn 768
#define Hn 12
#define DHn 64
#define Fn 3072
#define Ln 2
#define BSn (Bn*Sn)
#define BHn (Bn*Hn)
#define NTILES 16              // Sn / 128 score column tiles

// ---------------- scratch ----------------
__device__ float g_h  [BSn*Dn];     // full-precision residual stream
__device__ float g_hr [BSn*Dn];     // tf32-rounded copy for GEMM A operands
__device__ float g_qh [BSn*Dn];
__device__ float g_kh [BSn*Dn];
__device__ float g_vh [BSn*Dn];
__device__ float g_o  [2*BSn*Dn];   // AV partials (2 K-chunks)
__device__ float g_t  [2*BSn*Dn];   // Wo / W2 partials (2 K-chunks)
__device__ float g_ff [BSn*Fn];
__device__ float g_ssum[BHn*Sn*NTILES];
// tf32-rounded weight copies: Wq,Wk,Wv,Wo (L*D*D each), W1,W2 (L*D*F each)
#define WDD (Ln*Dn*Dn)
#define WDF (Ln*Dn*Fn)
__device__ float g_wr [4*WDD + 2*WDF];

__device__ __forceinline__ float rnd_tf32(float x) { return wmma::__float_to_tf32(x); }

// ---------------- cp.async helpers ----------------
__device__ __forceinline__ void cp_async16(uint32_t saddr, const void* gaddr) {
    asm volatile("cp.async.cg.shared.global [%0], [%1], 16;\n" :: "r"(saddr), "l"(gaddr));
}
#define CP_COMMIT() asm volatile("cp.async.commit_group;\n" ::)
#define CP_WAIT1()  asm volatile("cp.async.wait_group 1;\n" ::)
#define CP_WAIT0()  asm volatile("cp.async.wait_group 0;\n" ::)

// ---------------- fused weight rounding (all 6 weights, one launch) ----------------
__global__ void round_all_w(const float* __restrict__ Wq, const float* __restrict__ Wk,
                            const float* __restrict__ Wv, const float* __restrict__ Wo,
                            const float* __restrict__ W1, const float* __restrict__ W2,
                            float* __restrict__ dst)
{
    const long total4 = (4L*WDD + 2L*WDF) / 4;
    long i4 = (long)blockIdx.x * blockDim.x + threadIdx.x;
    if (i4 >= total4) return;
    long i = i4 * 4;
    const float* src; long off;
    if      (i <  (long)WDD)        { src = Wq; off = i; }
    else if (i < 2L*WDD)            { src = Wk; off = i - WDD; }
    else if (i < 3L*WDD)            { src = Wv; off = i - 2L*WDD; }
    else if (i < 4L*WDD)            { src = Wo; off = i - 3L*WDD; }
    else if (i < 4L*WDD + WDF)      { src = W1; off = i - 4L*WDD; }
    else                            { src = W2; off = i - 4L*WDD - WDF; }
    float4 v = *(const float4*)(src + off);
    v.x = rnd_tf32(v.x); v.y = rnd_tf32(v.y); v.z = rnd_tf32(v.z); v.w = rnd_tf32(v.w);
    *(float4*)(dst + i) = v;
}

// ---------------- embedding + sinusoidal PE ----------------
__global__ void embed_kernel(const int* __restrict__ x, const float* __restrict__ emb,
                             float* __restrict__ h, float* __restrict__ hr)
{
    int row = blockIdx.x;
    int s   = row % Sn;
    long tok = x[row];
    const float* er = emb + tok * (long)Dn;
    float* hp = h + (long)row * Dn;
    float* hq = hr + (long)row * Dn;
    const float c = -logf(10000.0f) / (float)Dn;
    for (int j = threadIdx.x; j < Dn; j += blockDim.x) {
        float div = expf((float)(j & ~1) * c);
        float ang = (float)s * div;
        float pe = (j & 1) ? cosf(ang) : sinf(ang);
        float v = er[j] + pe;
        hp[j] = v;
        hq[j] = rnd_tf32(v);
    }
}

// ============ specialized scores kernel: S = Q K^T (K=64, single-shot) ============
#define LDQK 68
#define LDSC 132
#define SMEM_SC ((2*128*LDQK)*4)    // 69632 bytes; epilogue alias needs 128*132*4=67584

__global__ __launch_bounds__(256, 2)
void scores_kernel(const float* __restrict__ qh, const float* __restrict__ kh,
                   float* __restrict__ maps, float* __restrict__ st_sum)
{
    extern __shared__ float sm[];
    float* Qs = sm;                 // [128][LDQK]
    float* Ks = Qs + 128*LDQK;      // [128][LDQK]
    float* Cs = sm;                 // epilogue alias [128][LDSC]

    const int z  = blockIdx.z;
    const int bm = blockIdx.y * 128;
    const int bn = blockIdx.x * 128;
    const int tid = threadIdx.x;
    const int warp = tid >> 5;
    const int lane = tid & 31;
    const int wm = (warp & 3) * 32;
    const int wn = (warp >> 2) * 64;

    const float* Qg = qh + ((long)z * Sn + bm) * DHn;
    const float* Kg = kh + ((long)z * Sn + bn) * DHn;
    const uint32_t sQ = (uint32_t)__cvta_generic_to_shared(Qs);
    const uint32_t sK = (uint32_t)__cvta_generic_to_shared(Ks);

#pragma unroll
    for (int p = 0; p < 8; p++) {
        int e = tid + p * 256;
        int r = e >> 4, c4 = (e & 15) * 4;
        cp_async16(sQ + (r * LDQK + c4) * 4, Qg + (long)r * DHn + c4);
        cp_async16(sK + (r * LDQK + c4) * 4, Kg + (long)r * DHn + c4);
    }
    CP_COMMIT(); CP_WAIT0();
    __syncthreads();

    wmma::fragment<wmma::accumulator, 16, 16, 8, float> acc[2][4];
#pragma unroll
    for (int i = 0; i < 2; i++)
#pragma unroll
        for (int j = 0; j < 4; j++) wmma::fill_fragment(acc[i][j], 0.0f);

#pragma unroll
    for (int kf = 0; kf < 8; kf++) {
        wmma::fragment<wmma::matrix_a, 16, 16, 8, wmma::precision::tf32, wmma::row_major> af[2];
#pragma unroll
        for (int i = 0; i < 2; i++)
            wmma::load_matrix_sync(af[i], Qs + (wm + i * 16) * LDQK + kf * 8, LDQK);
        wmma::fragment<wmma::matrix_b, 16, 16, 8, wmma::precision::tf32, wmma::col_major> bf[4];
#pragma unroll
        for (int j = 0; j < 4; j++)
            wmma::load_matrix_sync(bf[j], Ks + (wn + j * 16) * LDQK + kf * 8, LDQK);
#pragma unroll
        for (int i = 0; i < 2; i++)
#pragma unroll
            for (int j = 0; j < 4; j++)
                wmma::mma_sync(acc[i][j], af[i], bf[j], acc[i][j]);
    }

    __syncthreads();
#pragma unroll
    for (int i = 0; i < 2; i++)
#pragma unroll
        for (int j = 0; j < 4; j++)
            wmma::store_matrix_sync(Cs + (wm + i * 16) * LDSC + wn + j * 16,
                                    acc[i][j], LDSC, wmma::mem_row_major);
    __syncthreads();

    float* C = maps + (long)z * Sn * Sn;
#pragma unroll
    for (int p = 0; p < 16; p++) {
        int e  = tid + p * 256;
        int m  = e >> 5;
        int nv = (e & 31) * 4;
        float4 v = *(const float4*)&Cs[m * LDSC + nv];
        float ex = __expf(v.x * 0.125f), ey = __expf(v.y * 0.125f);
        float ez = __expf(v.z * 0.125f), ew = __expf(v.w * 0.125f);
        *(float4*)&C[(long)(bm + m) * Sn + bn + nv] = make_float4(ex, ey, ez, ew);
        float lsum = ex + ey + ez + ew;
#pragma unroll
        for (int o = 16; o > 0; o >>= 1)
            lsum += __shfl_xor_sync(0xffffffffu, lsum, o);
        if (lane == 0)
            st_sum[((long)z * Sn + bm + m) * NTILES + blockIdx.x] = lsum;
    }
}

// ---------------- pipelined TF32 tensor-core GEMM (256 thr, 8 warps) ----------------
// MODE: 0 plain, 1 heads (QKV -> [b,h,s,d]), 2 merge (AV -> [b,s,D])
// MULTI: z selects {B0,B1,B2}; non-MULTI z applies strides (batch OR K-chunk).
// SMAX: A holds exp(s); grid.x = K-chunk (bn forced 0); partial O to C + chunk
//       offset; probs (E*sc) written back to the chunk's columns of A.
template<int BM, int BN, int MODE, bool MULTI, bool SMAX>
__global__ __launch_bounds__(256, 2)
void gemm_tc(const float* __restrict__ A,
             const float* B0, const float* B1, const float* B2,
             const float* bias0, const float* bias1, const float* bias2,
             float* C0, float* C1, float* C2,
             int M, int N, int K, int lda, int ldb, int ldc,
             long sA, long sB, long sC, int relu, int rndout,
             float* st_sum)
{
    constexpr int BK = 32;
    constexpr int STAGES = 3;
    constexpr int LDA_S = BK + 4;
    constexpr int LDB_S = BN + 4;
    constexpr int LDC_S = BN + 4;
    constexpr int WARPS_M = 4, WARPS_N = 2;
    constexpr int WM = BM / WARPS_M;
    constexpr int WN = BN / WARPS_N;
    constexpr int FM = WM / 16;
    constexpr int FN = WN / 16;

    extern __shared__ char smem_raw[];
    float* As = (float*)smem_raw;                       // [STAGES][BM][LDA_S]
    float* Bs = As + STAGES * BM * LDA_S;               // [STAGES][BK][LDB_S]
    float* sm_scale = Bs + STAGES * BK * LDB_S;         // [BM] (SMAX only)
    float* Cs = (float*)smem_raw;                       // epilogue alias

    const int z = blockIdx.z;
    const float* Bm; const float* bias; float* C;
    if (MULTI) {
        Bm   = (z == 0) ? B0 : ((z == 1) ? B1 : B2);
        bias = (z == 0) ? bias0 : ((z == 1) ? bias1 : bias2);
        C    = (z == 0) ? C0 : ((z == 1) ? C1 : C2);
    } else {
        Bm   = B0 + z * sB;
        bias = bias0;
        C    = C0 + z * sC;
        A   += z * sA;
    }

    const int bm = blockIdx.y * BM;
    const int bn = SMAX ? 0 : blockIdx.x * BN;
    const int tid = threadIdx.x;
    const int warp = tid >> 5;
    const int wm = (warp % WARPS_M) * WM;
    const int wn = (warp / WARPS_M) * WN;

    if (SMAX) {
        // K-chunk select via grid.x (traffic-neutral CTA doubling)
        const int kc = blockIdx.x;
        A  += (long)kc * K;                     // chunk columns of exp-matrix
        Bm += (long)kc * K * ldb;               // chunk rows of V
        C  += (long)kc * ((long)BSn * Dn);      // partial O buffer
        // per-row prob scale = 1 / sum_t tile_sums
        if (tid < BM) {
            const float* ps = st_sum + ((long)z * Sn + bm + tid) * NTILES;
            float S = 0.f;
#pragma unroll
            for (int t = 0; t < NTILES; t++) S += ps[t];
            sm_scale[tid] = 1.f / S;
        }
    }

    const uint32_t sAs = (uint32_t)__cvta_generic_to_shared(As);
    const uint32_t sBs = (uint32_t)__cvta_generic_to_shared(Bs);

    // strength-reduced global pointers (advance per k-iter)
    const int a_row0 = tid >> 3;
    const int a_kv   = (tid & 7) * 4;
    const float* pA = A + (long)(bm + a_row0) * lda + a_kv;
    const long stepA = 32L * lda;
    constexpr int RPB = 256 / (BN / 4);
    const int b_row0 = tid / (BN / 4);
    const int b_nv   = (tid % (BN / 4)) * 4;
    const float* pB = Bm + (long)b_row0 * ldb + bn + b_nv;
    const long stepB = (long)RPB * ldb;
    const long advB  = (long)BK * ldb;

    wmma::fragment<wmma::accumulator, 16, 16, 8, float> acc[FM][FN];
#pragma unroll
    for (int i = 0; i < FM; i++)
#pragma unroll
        for (int j = 0; j < FN; j++) wmma::fill_fragment(acc[i][j], 0.0f);

    const int kIters = K / BK;

    auto load_stage = [&](int st, int ki) {
        if (ki < kIters) {
#pragma unroll
            for (int p = 0; p < BM / 32; p++)
                cp_async16(sAs + ((st * BM + a_row0 + p * 32) * LDA_S + a_kv) * 4,
                           pA + p * stepA);
#pragma unroll
            for (int p = 0; p < BK / RPB; p++)
                cp_async16(sBs + ((st * BK + b_row0 + p * RPB) * LDB_S + b_nv) * 4,
                           pB + p * stepB);
        }
        pA += BK;
        pB += advB;
    };

    for (int s = 0; s < STAGES - 1; s++) { load_stage(s, s); CP_COMMIT(); }

    for (int ki = 0; ki < kIters; ki++) {
        CP_WAIT1();
        __syncthreads();
        load_stage((ki + STAGES - 1) % STAGES, ki + STAGES - 1);
        CP_COMMIT();

        const int st = ki % STAGES;
        float* Ast = As + st * BM * LDA_S;
        const float* Bst = Bs + st * BK * LDB_S;

        if (SMAX) {
            // write final probs (E * sc) to gmem; smem keeps raw E for the MMA.
            const int k0 = ki * BK;
            float* Awb = const_cast<float*>(A);
            constexpr int NVA = BM * BK / 4;
#pragma unroll
            for (int e = tid; e < NVA; e += 256) {
                int m  = e >> 3;
                int kv = (e & 7) * 4;
                float sc = sm_scale[m];
                float4 s4 = *(float4*)&Ast[m * LDA_S + kv];
                *(float4*)&Awb[(long)(bm + m) * lda + k0 + kv] =
                    make_float4(s4.x * sc, s4.y * sc, s4.z * sc, s4.w * sc);
            }
        }

#pragma unroll
        for (int kf = 0; kf < BK / 8; kf++) {
            wmma::fragment<wmma::matrix_a, 16, 16, 8, wmma::precision::tf32, wmma::row_major> af[FM];
#pragma unroll
            for (int i = 0; i < FM; i++)
                wmma::load_matrix_sync(af[i], Ast + (wm + i * 16) * LDA_S + kf * 8, LDA_S);
            wmma::fragment<wmma::matrix_b, 16, 16, 8, wmma::precision::tf32, wmma::row_major> bf[FN];
#pragma unroll
            for (int j = 0; j < FN; j++)
                wmma::load_matrix_sync(bf[j], Bst + (kf * 8) * LDB_S + wn + j * 16, LDB_S);
#pragma unroll
            for (int i = 0; i < FM; i++)
#pragma unroll
                for (int j = 0; j < FN; j++)
                    wmma::mma_sync(acc[i][j], af[i], bf[j], acc[i][j]);
        }
    }

    CP_WAIT0();
    __syncthreads();

#pragma unroll
    for (int i = 0; i < FM; i++)
#pragma unroll
        for (int j = 0; j < FN; j++)
            wmma::store_matrix_sync(Cs + (wm + i * 16) * LDC_S + wn + j * 16,
                                    acc[i][j], LDC_S, wmma::mem_row_major);
    __syncthreads();

    constexpr int NVC = BM * BN / 4;
#pragma unroll 4
    for (int e = tid; e < NVC; e += 256) {
        int m  = e / (BN / 4);
        int nv = (e % (BN / 4)) * 4;
        float4 v = *(const float4*)&Cs[m * LDC_S + nv];
        if (SMAX) {
            float sc = sm_scale[m];
            v.x *= sc; v.y *= sc; v.z *= sc; v.w *= sc;
        }
        if (bias) {
            int c = bn + nv;
            v.x += bias[c]; v.y += bias[c + 1]; v.z += bias[c + 2]; v.w += bias[c + 3];
        }
        if (relu) {
            v.x = fmaxf(v.x, 0.f); v.y = fmaxf(v.y, 0.f);
            v.z = fmaxf(v.z, 0.f); v.w = fmaxf(v.w, 0.f);
        }
        if (rndout) {
            v.x = rnd_tf32(v.x); v.y = rnd_tf32(v.y);
            v.z = rnd_tf32(v.z); v.w = rnd_tf32(v.w);
        }
        if (MODE == 0) {
            *(float4*)&C[(long)(bm + m) * ldc + bn + nv] = v;
        } else if (MODE == 1) {
            int r = bm + m, c = bn + nv;
            int b = r >> 11, s = r & (Sn - 1);
            int hh = c >> 6, d = c & 63;
            *(float4*)&C[((((long)b * Hn + hh) * Sn + s) << 6) + d] = v;
        } else {
            int b = z / Hn, hh = z % Hn;
            *(float4*)&C[((long)(b * Sn + bm + m)) * Dn + hh * DHn + bn + nv] = v;
        }
    }
}

// ---------------- combine AV partials: o = o0 + o1 ----------------
__global__ void combine_o(float* __restrict__ o, const float* __restrict__ o2)
{
    long i4 = (long)blockIdx.x * blockDim.x + threadIdx.x;
    if (i4 >= (long)BSn * Dn / 4) return;
    long i = i4 * 4;
    float4 a = *(const float4*)(o + i);
    float4 b = *(const float4*)(o2 + i);
    a.x += b.x; a.y += b.y; a.z += b.z; a.w += b.w;
    *(float4*)(o + i) = a;
}

// ---------------- residual add(2 partials + bias) + LayerNorm ----------------
__global__ void add_ln_kernel(const float* __restrict__ x,
                              const float* __restrict__ d0, const float* __restrict__ d1,
                              const float* __restrict__ db,   // per-column bias (Wo/W2 bias)
                              const float* __restrict__ g, const float* __restrict__ bb,
                              float* __restrict__ outf, float* __restrict__ outr)
{
    int row = blockIdx.x;
    int t = threadIdx.x;
    __shared__ float red[256];
    float v[3];
    float s = 0.f;
#pragma unroll
    for (int i = 0; i < 3; i++) {
        int c = t + i*256;
        long idx = (long)row*Dn + c;
        v[i] = x[idx] + d0[idx] + d1[idx] + db[c];
        s += v[i];
    }
    red[t] = s; __syncthreads();
    for (int o = 128; o > 0; o >>= 1) { if (t < o) red[t] += red[t+o]; __syncthreads(); }
    float mu = red[0] / (float)Dn;
    __syncthreads();
    float s2 = 0.f;
#pragma unroll
    for (int i = 0; i < 3; i++) { float dv = v[i] - mu; s2 += dv*dv; }
    red[t] = s2; __syncthreads();
    for (int o = 128; o > 0; o >>= 1) { if (t < o) red[t] += red[t+o]; __syncthreads(); }
    float inv = rsqrtf(red[0] / (float)Dn + 1e-5f);
    __syncthreads();
#pragma unroll
    for (int i = 0; i < 3; i++) {
        int c = t + i*256;
        float r = (v[i] - mu) * inv * g[c] + bb[c];
        outf[(long)row*Dn + c] = r;
        if (outr) outr[(long)row*Dn + c] = rnd_tf32(r);
    }
}

// ---------------- host side ----------------
#define SYM_PTR(sym) ([]{ void* p_; cudaGetSymbolAddress(&p_, sym); return (float*)p_; }())

#define SMEM_NN128 ((3*(128*36 + 32*132))*4)            // 105984  (BN=128 dense)
#define SMEM_AV    ((3*(128*36 + 32*68) + 128)*4)       // 81920   (AV, incl. scale)
#define SMEM_NN64  ((3*(128*36 + 32*68))*4)             // 81408   (BN=64 dense)

extern "C" void kernel_launch(void* const* d_in, const int* in_sizes, int n_in,
                              void* d_out, int out_size)
{
    const int*   x    = (const int*)  d_in[0];
    const float* emb  = (const float*)d_in[1];
    const float* Wq   = (const float*)d_in[2];
    const float* bq   = (const float*)d_in[3];
    const float* Wk   = (const float*)d_in[4];
    const float* bk   = (const float*)d_in[5];
    const float* Wv   = (const float*)d_in[6];
    const float* bv   = (const float*)d_in[7];
    const float* Wo   = (const float*)d_in[8];
    const float* bo   = (const float*)d_in[9];
    const float* ln1g = (const float*)d_in[10];
    const float* ln1b = (const float*)d_in[11];
    const float* ln2g = (const float*)d_in[12];
    const float* ln2b = (const float*)d_in[13];
    const float* W1   = (const float*)d_in[14];
    const float* b1   = (const float*)d_in[15];
    const float* W2   = (const float*)d_in[16];
    const float* b2   = (const float*)d_in[17];

    float* out = (float*)d_out;

    float* h    = SYM_PTR(g_h);
    float* hr   = SYM_PTR(g_hr);
    float* qh   = SYM_PTR(g_qh);
    float* kh   = SYM_PTR(g_kh);
    float* vh   = SYM_PTR(g_vh);
    float* o    = SYM_PTR(g_o);
    float* t    = SYM_PTR(g_t);
    float* ff   = SYM_PTR(g_ff);
    float* ssum = SYM_PTR(g_ssum);
    float* wr   = SYM_PTR(g_wr);

    float* Wq_r = wr;
    float* Wk_r = Wq_r + WDD;
    float* Wv_r = Wk_r + WDD;
    float* Wo_r = Wv_r + WDD;
    float* W1_r = Wo_r + WDD;
    float* W2_r = W1_r + WDF;

    cudaFuncSetAttribute(gemm_tc<128,128,1,true ,false>, cudaFuncAttributeMaxDynamicSharedMemorySize, SMEM_NN128);
    cudaFuncSetAttribute(gemm_tc<128,128,0,false,false>, cudaFuncAttributeMaxDynamicSharedMemorySize, SMEM_NN128);
    cudaFuncSetAttribute(gemm_tc<128,64 ,2,false,true >, cudaFuncAttributeMaxDynamicSharedMemorySize, SMEM_AV);
    cudaFuncSetAttribute(gemm_tc<128,64 ,0,false,false>, cudaFuncAttributeMaxDynamicSharedMemorySize, SMEM_NN64);
    cudaFuncSetAttribute(scores_kernel, cudaFuncAttributeMaxDynamicSharedMemorySize, SMEM_SC);

    {
        long total4 = (4L*WDD + 2L*WDF) / 4;
        round_all_w<<<(int)((total4 + 255)/256), 256>>>(Wq, Wk, Wv, Wo, W1, W2, wr);
    }
    embed_kernel<<<BSn, 256>>>(x, emb, h, hr);

    const int COMB_BLOCKS = (int)(((long)BSn*Dn/4 + 255) / 256);

    for (int l = 0; l < Ln; l++) {
        const float* Wq_l = Wq_r + (long)l*Dn*Dn; const float* bq_l = bq + (long)l*Dn;
        const float* Wk_l = Wk_r + (long)l*Dn*Dn; const float* bk_l = bk + (long)l*Dn;
        const float* Wv_l = Wv_r + (long)l*Dn*Dn; const float* bv_l = bv + (long)l*Dn;
        const float* Wo_l = Wo_r + (long)l*Dn*Dn; const float* bo_l = bo + (long)l*Dn;
        const float* W1_l = W1_r + (long)l*Dn*Fn; const float* b1_l = b1 + (long)l*Fn;
        const float* W2_l = W2_r + (long)l*Fn*Dn; const float* b2_l = b2 + (long)l*Dn;
        float* maps = out + (long)BSn*Dn + (long)l*Bn*Hn*Sn*Sn;

        // QKV fused -> head layout (outputs tf32-rounded; A = rounded hr)
        {
            dim3 grid(Dn/128, BSn/128, 3);
            gemm_tc<128,128,1,true,false><<<grid,256,SMEM_NN128>>>(
                hr, Wq_l, Wk_l, Wv_l, bq_l, bk_l, bv_l, qh, kh, vh,
                BSn, Dn, Dn, Dn, Dn, 0, 0,0,0, 0, 1,
                nullptr);
        }
        // scores: single-shot kernel (exp(s/8) to maps + tile sums)
        {
            dim3 grid(Sn/128, Sn/128, BHn);
            scores_kernel<<<grid,256,SMEM_SC>>>(qh, kh, maps, ssum);
        }
        // O = (E @ V) * sc, K-split 2 (grid.x = chunk); probs to maps; partials to o[0],o[1]
        {
            dim3 grid(2, Sn/128, BHn);
            gemm_tc<128,64,2,false,true><<<grid,256,SMEM_AV>>>(
                maps, vh, nullptr, nullptr, nullptr, nullptr, nullptr,
                o, nullptr, nullptr,
                Sn, DHn, Sn/2, Sn, DHn, 0,
                (long)Sn*Sn, (long)Sn*DHn, 0, 0, 1,
                ssum);
        }
        combine_o<<<COMB_BLOCKS,256>>>(o, o + (long)BSn*Dn);
        // attn_out partials: t_c = o @ Wo[kc]  (K-split 2 via grid.z; bias folded into LN1)
        {
            dim3 grid(Dn/64, BSn/128, 2);
            gemm_tc<128,64,0,false,false><<<grid,256,SMEM_NN64>>>(
                o, Wo_l, nullptr, nullptr, nullptr, nullptr, nullptr,
                t, nullptr, nullptr,
                BSn, Dn, Dn/2, Dn, Dn, Dn,
                (long)(Dn/2), (long)(Dn/2)*Dn, (long)BSn*Dn, 0, 0,
                nullptr);
        }
        add_ln_kernel<<<BSn,256>>>(h, t, t + (long)BSn*Dn, bo_l,
                                   ln1g + (long)l*Dn, ln1b + (long)l*Dn, h, hr);
        // ff = relu(hr @ W1 + b1)  (768 CTAs already; keep single-chunk)
        {
            dim3 grid(Fn/128, BSn/128, 1);
            gemm_tc<128,128,0,false,false><<<grid,256,SMEM_NN128>>>(
                hr, W1_l, nullptr, nullptr, b1_l, nullptr, nullptr,
                ff, nullptr, nullptr,
                BSn, Fn, Dn, Dn, Fn, Fn, 0,0,0, 1, 1,
                nullptr);
        }
        // t_c = ff @ W2[kc]  (K-split 2 via grid.z; bias folded into LN2)
        {
            dim3 grid(Dn/64, BSn/128, 2);
            gemm_tc<128,64,0,false,false><<<grid,256,SMEM_NN64>>>(
                ff, W2_l, nullptr, nullptr, nullptr, nullptr, nullptr,
                t, nullptr, nullptr,
                BSn, Dn, Fn/2, Fn, Dn, Dn,
                (long)(Fn/2), (long)(Fn/2)*Dn, (long)BSn*Dn, 0, 0,
                nullptr);
        }
        if (l == Ln-1)
            add_ln_kernel<<<BSn,256>>>(h, t, t + (long)BSn*Dn, b2_l,
                                       ln2g + (long)l*Dn, ln2b + (long)l*Dn, out, nullptr);
        else
            add_ln_kernel<<<BSn,256>>>(h, t, t + (long)BSn*Dn, b2_l,
                                       ln2g + (long)l*Dn, ln2b + (long)l*Dn, h, hr);
    }
}

// round 17
// speedup vs baseline: 2.5593x; 2.1789x over previous
#include <cuda_runtime.h>
#include <mma.h>
#include <cuda_fp16.h>
#include <math.h>
#include <cstdint>
#include <stdint.h>

using namespace nvcuda;

#define Bn 2
#define Sn 2048
#define Dn 768
#define Hn 12
#define DHn 64
#define Fn 3072
#define Ln 2
#define BSn (Bn*Sn)
#define BHn (Bn*Hn)
#define NTILES 16              // Sn / 128 score column tiles

// ---------------- scratch ----------------
__device__ float  g_h  [BSn*Dn];     // full-precision residual stream
__device__ __half g_hh [BSn*Dn];     // half copy for GEMM A operands
__device__ __half g_qh [BSn*Dn];
__device__ __half g_kh [BSn*Dn];
__device__ float  g_v32[BSn*Dn];     // V stays fp32 (AV kernel is tf32)
__device__ float  g_o  [2*BSn*Dn];   // AV partials (2 K-chunks, fp32)
__device__ __half g_ohh[BSn*Dn];     // combined O, half (Wo input)
__device__ float  g_t  [2*BSn*Dn];   // Wo / W2 partials (fp32)
__device__ __half g_ffh[BSn*Fn];     // FFN hidden, half (W2 input)
__device__ float  g_ssum[BHn*Sn*NTILES];
// half weight copies: Wq,Wk,Wv,Wo (L*D*D each), W1,W2 (L*D*F each)
#define WDD (Ln*Dn*Dn)
#define WDF (Ln*Dn*Fn)
__device__ __half g_wh [4*WDD + 2*WDF];

// ---------------- cp.async helpers ----------------
__device__ __forceinline__ void cp_async16(uint32_t saddr, const void* gaddr) {
    asm volatile("cp.async.cg.shared.global [%0], [%1], 16;\n" :: "r"(saddr), "l"(gaddr));
}
#define CP_COMMIT() asm volatile("cp.async.commit_group;\n" ::)
#define CP_WAIT1()  asm volatile("cp.async.wait_group 1;\n" ::)
#define CP_WAIT0()  asm volatile("cp.async.wait_group 0;\n" ::)

__device__ __forceinline__ void store_half4(__half* p, float4 v) {
    __half2 p0 = __floats2half2_rn(v.x, v.y);
    __half2 p1 = __floats2half2_rn(v.z, v.w);
    uint2 u;
    u.x = *(unsigned*)&p0;
    u.y = *(unsigned*)&p1;
    *(uint2*)p = u;
}

// ---------------- weight conversion fp32 -> half (one launch) ----------------
__global__ void conv_all_w(const float* __restrict__ Wq, const float* __restrict__ Wk,
                           const float* __restrict__ Wv, const float* __restrict__ Wo,
                           const float* __restrict__ W1, const float* __restrict__ W2,
                           __half* __restrict__ dst)
{
    const long total4 = (4L*WDD + 2L*WDF) / 4;
    long i4 = (long)blockIdx.x * blockDim.x + threadIdx.x;
    if (i4 >= total4) return;
    long i = i4 * 4;
    const float* src; long off;
    if      (i <  (long)WDD)        { src = Wq; off = i; }
    else if (i < 2L*WDD)            { src = Wk; off = i - WDD; }
    else if (i < 3L*WDD)            { src = Wv; off = i - 2L*WDD; }
    else if (i < 4L*WDD)            { src = Wo; off = i - 3L*WDD; }
    else if (i < 4L*WDD + WDF)      { src = W1; off = i - 4L*WDD; }
    else                            { src = W2; off = i - 4L*WDD - WDF; }
    float4 v = *(const float4*)(src + off);
    store_half4(dst + i, v);
}

// ---------------- embedding + sinusoidal PE ----------------
__global__ void embed_kernel(const int* __restrict__ x, const float* __restrict__ emb,
                             float* __restrict__ h, __half* __restrict__ hh)
{
    int row = blockIdx.x;
    int s   = row % Sn;
    long tok = x[row];
    const float* er = emb + tok * (long)Dn;
    float* hp = h + (long)row * Dn;
    __half* hq = hh + (long)row * Dn;
    const float c = -logf(10000.0f) / (float)Dn;
    for (int j = threadIdx.x; j < Dn; j += blockDim.x) {
        float div = expf((float)(j & ~1) * c);
        float ang = (float)s * div;
        float pe = (j & 1) ? cosf(ang) : sinf(ang);
        float v = er[j] + pe;
        hp[j] = v;
        hq[j] = __float2half(v);
    }
}

// ============ scores kernel: S = Q K^T (half inputs, fp32 acc, single-shot) ============
#define LDQK 72     // halfs (144B, 16B-multiple)
#define LDSC 132
#define SMEM_SC (128*LDSC*4)    // 67584; half tiles (2*128*72*2=36864) fit under alias

__global__ __launch_bounds__(256, 2)
void scores_kernel(const __half* __restrict__ qh, const __half* __restrict__ kh,
                   float* __restrict__ maps, float* __restrict__ st_sum)
{
    extern __shared__ char smc[];
    __half* Qs = (__half*)smc;          // [128][LDQK]
    __half* Ks = Qs + 128*LDQK;         // [128][LDQK]
    float*  Cs = (float*)smc;           // epilogue alias [128][LDSC]

    const int z  = blockIdx.z;
    const int bm = blockIdx.y * 128;
    const int bn = blockIdx.x * 128;
    const int tid = threadIdx.x;
    const int warp = tid >> 5;
    const int lane = tid & 31;
    const int wm = (warp & 3) * 32;
    const int wn = (warp >> 2) * 64;

    const __half* Qg = qh + ((long)z * Sn + bm) * DHn;
    const __half* Kg = kh + ((long)z * Sn + bn) * DHn;
    const uint32_t sQ = (uint32_t)__cvta_generic_to_shared(Qs);
    const uint32_t sK = (uint32_t)__cvta_generic_to_shared(Ks);

    // each tile: 128 rows x 8 chunks of 8 halfs
#pragma unroll
    for (int p = 0; p < 4; p++) {
        int e = tid + p * 256;
        int r = e >> 3, c8 = (e & 7) * 8;
        cp_async16(sQ + (r * LDQK + c8) * 2, Qg + (long)r * DHn + c8);
        cp_async16(sK + (r * LDQK + c8) * 2, Kg + (long)r * DHn + c8);
    }
    CP_COMMIT(); CP_WAIT0();
    __syncthreads();

    wmma::fragment<wmma::accumulator, 16, 16, 16, float> acc[2][4];
#pragma unroll
    for (int i = 0; i < 2; i++)
#pragma unroll
        for (int j = 0; j < 4; j++) wmma::fill_fragment(acc[i][j], 0.0f);

#pragma unroll
    for (int kf = 0; kf < 4; kf++) {
        wmma::fragment<wmma::matrix_a, 16, 16, 16, __half, wmma::row_major> af[2];
#pragma unroll
        for (int i = 0; i < 2; i++)
            wmma::load_matrix_sync(af[i], Qs + (wm + i * 16) * LDQK + kf * 16, LDQK);
        wmma::fragment<wmma::matrix_b, 16, 16, 16, __half, wmma::col_major> bf[4];
#pragma unroll
        for (int j = 0; j < 4; j++)
            wmma::load_matrix_sync(bf[j], Ks + (wn + j * 16) * LDQK + kf * 16, LDQK);
#pragma unroll
        for (int i = 0; i < 2; i++)
#pragma unroll
            for (int j = 0; j < 4; j++)
                wmma::mma_sync(acc[i][j], af[i], bf[j], acc[i][j]);
    }

    __syncthreads();
#pragma unroll
    for (int i = 0; i < 2; i++)
#pragma unroll
        for (int j = 0; j < 4; j++)
            wmma::store_matrix_sync(Cs + (wm + i * 16) * LDSC + wn + j * 16,
                                    acc[i][j], LDSC, wmma::mem_row_major);
    __syncthreads();

    float* C = maps + (long)z * Sn * Sn;
#pragma unroll
    for (int p = 0; p < 16; p++) {
        int e  = tid + p * 256;
        int m  = e >> 5;
        int nv = (e & 31) * 4;
        float4 v = *(const float4*)&Cs[m * LDSC + nv];
        float ex = __expf(v.x * 0.125f), ey = __expf(v.y * 0.125f);
        float ez = __expf(v.z * 0.125f), ew = __expf(v.w * 0.125f);
        *(float4*)&C[(long)(bm + m) * Sn + bn + nv] = make_float4(ex, ey, ez, ew);
        float lsum = ex + ey + ez + ew;
#pragma unroll
        for (int o = 16; o > 0; o >>= 1)
            lsum += __shfl_xor_sync(0xffffffffu, lsum, o);
        if (lane == 0)
            st_sum[((long)z * Sn + bm + m) * NTILES + blockIdx.x] = lsum;
    }
}

// ---------------- pipelined FP16 tensor-core GEMM (fp32 accumulate) ----------------
// MODE: 0 plain, 1 heads (QKV -> [b,h,s,d]; z<2 -> half out, z==2 -> fp32 out)
// MULTI: z selects {B0,B1,B2}; non-MULTI z = K-chunk (fp32 partial outputs).
// HOUT: MODE0 output dtype (half for activations feeding GEMMs, fp32 for partials).
template<int BM, int BN, int MODE, bool MULTI, bool HOUT>
__global__ __launch_bounds__(256, 2)
void gemm_h(const __half* __restrict__ A,
            const __half* B0, const __half* B1, const __half* B2,
            const float* bias0, const float* bias1, const float* bias2,
            void* C0v, void* C1v, void* C2v,
            int M, int N, int K, int lda, int ldb, int ldc,
            long sA, long sB, long sC, int relu)
{
    constexpr int BK = 32;
    constexpr int STAGES = 3;
    constexpr int LDA_S = BK + 8;     // 40 halfs (80B)
    constexpr int LDB_S = BN + 8;     // 136 / 72 halfs
    constexpr int LDC_S = BN + 4;     // fp32 epilogue
    constexpr int WM = BM / 4;        // 32
    constexpr int WN = BN / 2;        // 64 / 32
    constexpr int FM = WM / 16;       // 2
    constexpr int FN = WN / 16;       // 4 / 2

    extern __shared__ char smem_raw[];
    __half* As = (__half*)smem_raw;                 // [STAGES][BM][LDA_S]
    __half* Bs = As + STAGES * BM * LDA_S;          // [STAGES][BK][LDB_S]
    float*  Cs = (float*)smem_raw;                  // epilogue alias

    const int z = blockIdx.z;
    const __half* Bm; const float* bias; void* Cv;
    if (MULTI) {
        Bm   = (z == 0) ? B0 : ((z == 1) ? B1 : B2);
        bias = (z == 0) ? bias0 : ((z == 1) ? bias1 : bias2);
        Cv   = (z == 0) ? C0v : ((z == 1) ? C1v : C2v);
    } else {
        Bm   = B0 + z * sB;
        bias = bias0;
        Cv   = (char*)C0v + z * sC * 4;   // fp32 partials for K-split
        A   += z * sA;
    }

    const int bm = blockIdx.y * BM;
    const int bn = blockIdx.x * BN;
    const int tid = threadIdx.x;
    const int warp = tid >> 5;
    const int wm = (warp & 3) * WM;
    const int wn = (warp >> 2) * WN;

    const uint32_t sAs = (uint32_t)__cvta_generic_to_shared(As);
    const uint32_t sBs = (uint32_t)__cvta_generic_to_shared(Bs);

    // A tile: BM x 32 halfs -> 128 rows x 4 chunks(8h); 2 passes of 64 rows
    const int a_row0 = tid >> 2;
    const int a_kv   = (tid & 3) * 8;
    const __half* pA = A + (long)(bm + a_row0) * lda + a_kv;
    const long stepA = 64L * lda;
    // B tile: 32 x BN halfs
    constexpr int CPR = BN / 8;              // chunks per row (16 or 8)
    constexpr int RPB = 256 / CPR;           // rows per pass (16 or 32)
    const int b_row0 = tid / CPR;
    const int b_nv   = (tid % CPR) * 8;
    const __half* pB = Bm + (long)b_row0 * ldb + bn + b_nv;
    const long stepB = (long)RPB * ldb;
    const long advB  = 32L * ldb;

    wmma::fragment<wmma::accumulator, 16, 16, 16, float> acc[FM][FN];
#pragma unroll
    for (int i = 0; i < FM; i++)
#pragma unroll
        for (int j = 0; j < FN; j++) wmma::fill_fragment(acc[i][j], 0.0f);

    const int kIters = K / BK;

    auto load_stage = [&](int st, int ki) {
        if (ki < kIters) {
#pragma unroll
            for (int p = 0; p < 2; p++)
                cp_async16(sAs + ((st * BM + a_row0 + p * 64) * LDA_S + a_kv) * 2,
                           pA + p * stepA);
#pragma unroll
            for (int p = 0; p < 32 / RPB; p++)
                cp_async16(sBs + ((st * 32 + b_row0 + p * RPB) * LDB_S + b_nv) * 2,
                           pB + p * stepB);
        }
        pA += BK;
        pB += advB;
    };

    for (int s = 0; s < STAGES - 1; s++) { load_stage(s, s); CP_COMMIT(); }

    for (int ki = 0; ki < kIters; ki++) {
        CP_WAIT1();
        __syncthreads();
        load_stage((ki + STAGES - 1) % STAGES, ki + STAGES - 1);
        CP_COMMIT();

        const int st = ki % STAGES;
        const __half* Ast = As + st * BM * LDA_S;
        const __half* Bst = Bs + st * 32 * LDB_S;

#pragma unroll
        for (int kf = 0; kf < 2; kf++) {
            wmma::fragment<wmma::matrix_a, 16, 16, 16, __half, wmma::row_major> af[FM];
#pragma unroll
            for (int i = 0; i < FM; i++)
                wmma::load_matrix_sync(af[i], Ast + (wm + i * 16) * LDA_S + kf * 16, LDA_S);
            wmma::fragment<wmma::matrix_b, 16, 16, 16, __half, wmma::row_major> bf[FN];
#pragma unroll
            for (int j = 0; j < FN; j++)
                wmma::load_matrix_sync(bf[j], Bst + (kf * 16) * LDB_S + wn + j * 16, LDB_S);
#pragma unroll
            for (int i = 0; i < FM; i++)
#pragma unroll
                for (int j = 0; j < FN; j++)
                    wmma::mma_sync(acc[i][j], af[i], bf[j], acc[i][j]);
        }
    }

    CP_WAIT0();
    __syncthreads();

#pragma unroll
    for (int i = 0; i < FM; i++)
#pragma unroll
        for (int j = 0; j < FN; j++)
            wmma::store_matrix_sync(Cs + (wm + i * 16) * LDC_S + wn + j * 16,
                                    acc[i][j], LDC_S, wmma::mem_row_major);
    __syncthreads();

    constexpr int NVC = BM * BN / 4;
#pragma unroll 4
    for (int e = tid; e < NVC; e += 256) {
        int m  = e / (BN / 4);
        int nv = (e % (BN / 4)) * 4;
        float4 v = *(const float4*)&Cs[m * LDC_S + nv];
        if (bias) {
            int c = bn + nv;
            v.x += bias[c]; v.y += bias[c + 1]; v.z += bias[c + 2]; v.w += bias[c + 3];
        }
        if (relu) {
            v.x = fmaxf(v.x, 0.f); v.y = fmaxf(v.y, 0.f);
            v.z = fmaxf(v.z, 0.f); v.w = fmaxf(v.w, 0.f);
        }
        if (MODE == 0) {
            long off = (long)(bm + m) * ldc + bn + nv;
            if (HOUT) store_half4((__half*)Cv + off, v);
            else      *(float4*)((float*)Cv + off) = v;
        } else {
            int r = bm + m, c = bn + nv;
            int b = r >> 11, s = r & (Sn - 1);
            int hh2 = c >> 6, d = c & 63;
            long off = ((((long)b * Hn + hh2) * Sn + s) << 6) + d;
            if (z < 2) store_half4((__half*)Cv + off, v);          // q, k
            else       *(float4*)((float*)Cv + off) = v;           // v (fp32 for AV)
        }
    }
}

// ---------------- AV kernel (TF32 path, fp32 maps in/out), K-split via grid.x ----------------
#define SMEM_AV ((3*(128*36 + 32*68) + 128)*4)   // 81920

__global__ __launch_bounds__(256, 2)
void av_kernel(const float* __restrict__ maps, const float* __restrict__ vh,
               float* __restrict__ og, const float* __restrict__ st_sum)
{
    constexpr int LDA_S = 36, LDB_S = 68, LDC_S = 68;
    constexpr int KC = Sn / 2;          // K per chunk
    extern __shared__ char smav[];
    float* As = (float*)smav;                       // [3][128][36]
    float* Bs = As + 3 * 128 * LDA_S;               // [3][32][68]
    float* sm_scale = Bs + 3 * 32 * LDB_S;          // [128]
    float* Cs = (float*)smav;

    const int z  = blockIdx.z;
    const int kc = blockIdx.x;
    const int bm = blockIdx.y * 128;
    const int tid = threadIdx.x;
    const int warp = tid >> 5;
    const int wm = (warp & 3) * 32;
    const int wn = (warp >> 2) * 32;

    const float* A  = maps + (long)z * Sn * Sn + (long)kc * KC;
    const float* Bm = vh + (long)z * Sn * DHn + (long)kc * KC * DHn;
    float* C = og + (long)kc * ((long)BSn * Dn);

    if (tid < 128) {
        const float* ps = st_sum + ((long)z * Sn + bm + tid) * NTILES;
        float S = 0.f;
#pragma unroll
        for (int t = 0; t < NTILES; t++) S += ps[t];
        sm_scale[tid] = 1.f / S;
    }

    const uint32_t sAs = (uint32_t)__cvta_generic_to_shared(As);
    const uint32_t sBs = (uint32_t)__cvta_generic_to_shared(Bs);

    const int a_row0 = tid >> 3;
    const int a_kv   = (tid & 7) * 4;
    const float* pA = A + (long)(bm + a_row0) * Sn + a_kv;
    const int b_row0 = tid / 16;
    const int b_nv   = (tid % 16) * 4;
    const float* pB = Bm + (long)b_row0 * DHn + b_nv;

    wmma::fragment<wmma::accumulator, 16, 16, 8, float> acc[2][2];
#pragma unroll
    for (int i = 0; i < 2; i++)
#pragma unroll
        for (int j = 0; j < 2; j++) wmma::fill_fragment(acc[i][j], 0.0f);

    const int kIters = KC / 32;

    auto load_stage = [&](int st, int ki) {
        if (ki < kIters) {
#pragma unroll
            for (int p = 0; p < 4; p++)
                cp_async16(sAs + ((st * 128 + a_row0 + p * 32) * LDA_S + a_kv) * 4,
                           pA + (long)p * 32 * Sn);
#pragma unroll
            for (int p = 0; p < 2; p++)
                cp_async16(sBs + ((st * 32 + b_row0 + p * 16) * LDB_S + b_nv) * 4,
                           pB + (long)p * 16 * DHn);
        }
        pA += 32;
        pB += 32L * DHn;
    };

    for (int s = 0; s < 2; s++) { load_stage(s, s); CP_COMMIT(); }

    for (int ki = 0; ki < kIters; ki++) {
        CP_WAIT1();
        __syncthreads();
        load_stage((ki + 2) % 3, ki + 2);
        CP_COMMIT();

        const int st = ki % 3;
        float* Ast = As + st * 128 * LDA_S;
        const float* Bst = Bs + st * 32 * LDB_S;

        // write final probs (E * sc) to gmem; smem keeps raw E for the MMA
        {
            const int k0 = ki * 32;
            float* Awb = const_cast<float*>(A);
#pragma unroll
            for (int e = tid; e < 128 * 8; e += 256) {
                int m  = e >> 3;
                int kv = (e & 7) * 4;
                float sc = sm_scale[m];
                float4 s4 = *(float4*)&Ast[m * LDA_S + kv];
                *(float4*)&Awb[(long)(bm + m) * Sn + k0 + kv] =
                    make_float4(s4.x * sc, s4.y * sc, s4.z * sc, s4.w * sc);
            }
        }

#pragma unroll
        for (int kf = 0; kf < 4; kf++) {
            wmma::fragment<wmma::matrix_a, 16, 16, 8, wmma::precision::tf32, wmma::row_major> af[2];
#pragma unroll
            for (int i = 0; i < 2; i++)
                wmma::load_matrix_sync(af[i], Ast + (wm + i * 16) * LDA_S + kf * 8, LDA_S);
            wmma::fragment<wmma::matrix_b, 16, 16, 8, wmma::precision::tf32, wmma::row_major> bf[2];
#pragma unroll
            for (int j = 0; j < 2; j++)
                wmma::load_matrix_sync(bf[j], Bst + (kf * 8) * LDB_S + wn + j * 16, LDB_S);
#pragma unroll
            for (int i = 0; i < 2; i++)
#pragma unroll
                for (int j = 0; j < 2; j++)
                    wmma::mma_sync(acc[i][j], af[i], bf[j], acc[i][j]);
        }
    }

    CP_WAIT0();
    __syncthreads();
#pragma unroll
    for (int i = 0; i < 2; i++)
#pragma unroll
        for (int j = 0; j < 2; j++)
            wmma::store_matrix_sync(Cs + (wm + i * 16) * LDC_S + wn + j * 16,
                                    acc[i][j], LDC_S, wmma::mem_row_major);
    __syncthreads();

    const int b = z / Hn, hh2 = z % Hn;
#pragma unroll
    for (int p = 0; p < 8; p++) {
        int e  = tid + p * 256;
        int m  = e >> 4;
        int nv = (e & 15) * 4;
        float4 v = *(const float4*)&Cs[m * LDC_S + nv];
        float sc = sm_scale[m];
        v.x *= sc; v.y *= sc; v.z *= sc; v.w *= sc;
        *(float4*)&C[(long)(b * Sn + bm + m) * Dn + hh2 * DHn + nv] = v;
    }
}

// ---------------- combine AV partials -> half O ----------------
__global__ void combine_o(const float* __restrict__ o0, const float* __restrict__ o1,
                          __half* __restrict__ oh)
{
    long i4 = (long)blockIdx.x * blockDim.x + threadIdx.x;
    if (i4 >= (long)BSn * Dn / 4) return;
    long i = i4 * 4;
    float4 a = *(const float4*)(o0 + i);
    float4 b = *(const float4*)(o1 + i);
    a.x += b.x; a.y += b.y; a.z += b.z; a.w += b.w;
    store_half4(oh + i, a);
}

// ---------------- residual add(2 partials + bias) + LayerNorm ----------------
__global__ void add_ln_kernel(const float* __restrict__ x,
                              const float* __restrict__ d0, const float* __restrict__ d1,
                              const float* __restrict__ db,
                              const float* __restrict__ g, const float* __restrict__ bb,
                              float* __restrict__ outf, __half* __restrict__ outh)
{
    int row = blockIdx.x;
    int t = threadIdx.x;
    __shared__ float red[256];
    float v[3];
    float s = 0.f;
#pragma unroll
    for (int i = 0; i < 3; i++) {
        int c = t + i*256;
        long idx = (long)row*Dn + c;
        v[i] = x[idx] + d0[idx] + d1[idx] + db[c];
        s += v[i];
    }
    red[t] = s; __syncthreads();
    for (int o = 128; o > 0; o >>= 1) { if (t < o) red[t] += red[t+o]; __syncthreads(); }
    float mu = red[0] / (float)Dn;
    __syncthreads();
    float s2 = 0.f;
#pragma unroll
    for (int i = 0; i < 3; i++) { float dv = v[i] - mu; s2 += dv*dv; }
    red[t] = s2; __syncthreads();
    for (int o = 128; o > 0; o >>= 1) { if (t < o) red[t] += red[t+o]; __syncthreads(); }
    float inv = rsqrtf(red[0] / (float)Dn + 1e-5f);
    __syncthreads();
#pragma unroll
    for (int i = 0; i < 3; i++) {
        int c = t + i*256;
        float r = (v[i] - mu) * inv * g[c] + bb[c];
        outf[(long)row*Dn + c] = r;
        if (outh) outh[(long)row*Dn + c] = __float2half(r);
    }
}

// ---------------- host side ----------------
#define SYM_PTR(sym, T) ([]{ void* p_; cudaGetSymbolAddress(&p_, sym); return (T*)p_; }())

#define SMEM_H128 (128*132*4)                               // 67584 (stages 56832 fit under alias)
#define SMEM_H64  ((3*(128*40 + 32*72))*2)                  // 44544 (Cs 34816 fits under alias)

extern "C" void kernel_launch(void* const* d_in, const int* in_sizes, int n_in,
                              void* d_out, int out_size)
{
    const int*   x    = (const int*)  d_in[0];
    const float* emb  = (const float*)d_in[1];
    const float* Wq   = (const float*)d_in[2];
    const float* bq   = (const float*)d_in[3];
    const float* Wk   = (const float*)d_in[4];
    const float* bk   = (const float*)d_in[5];
    const float* Wv   = (const float*)d_in[6];
    const float* bv   = (const float*)d_in[7];
    const float* Wo   = (const float*)d_in[8];
    const float* bo   = (const float*)d_in[9];
    const float* ln1g = (const float*)d_in[10];
    const float* ln1b = (const float*)d_in[11];
    const float* ln2g = (const float*)d_in[12];
    const float* ln2b = (const float*)d_in[13];
    const float* W1   = (const float*)d_in[14];
    const float* b1   = (const float*)d_in[15];
    const float* W2   = (const float*)d_in[16];
    const float* b2   = (const float*)d_in[17];

    float* out = (float*)d_out;

    float*  h    = SYM_PTR(g_h, float);
    __half* hh   = SYM_PTR(g_hh, __half);
    __half* qh   = SYM_PTR(g_qh, __half);
    __half* kh   = SYM_PTR(g_kh, __half);
    float*  v32  = SYM_PTR(g_v32, float);
    float*  o    = SYM_PTR(g_o, float);
    __half* ohh  = SYM_PTR(g_ohh, __half);
    float*  t    = SYM_PTR(g_t, float);
    __half* ffh  = SYM_PTR(g_ffh, __half);
    float*  ssum = SYM_PTR(g_ssum, float);
    __half* wh   = SYM_PTR(g_wh, __half);

    __half* Wq_h = wh;
    __half* Wk_h = Wq_h + WDD;
    __half* Wv_h = Wk_h + WDD;
    __half* Wo_h = Wv_h + WDD;
    __half* W1_h = Wo_h + WDD;
    __half* W2_h = W1_h + WDF;

    cudaFuncSetAttribute(gemm_h<128,128,1,true ,false>, cudaFuncAttributeMaxDynamicSharedMemorySize, SMEM_H128);
    cudaFuncSetAttribute(gemm_h<128,128,0,false,true >, cudaFuncAttributeMaxDynamicSharedMemorySize, SMEM_H128);
    cudaFuncSetAttribute(gemm_h<128,64 ,0,false,false>, cudaFuncAttributeMaxDynamicSharedMemorySize, SMEM_H64);
    cudaFuncSetAttribute(av_kernel,     cudaFuncAttributeMaxDynamicSharedMemorySize, SMEM_AV);
    cudaFuncSetAttribute(scores_kernel, cudaFuncAttributeMaxDynamicSharedMemorySize, SMEM_SC);

    {
        long total4 = (4L*WDD + 2L*WDF) / 4;
        conv_all_w<<<(int)((total4 + 255)/256), 256>>>(Wq, Wk, Wv, Wo, W1, W2, wh);
    }
    embed_kernel<<<BSn, 256>>>(x, emb, h, hh);

    const int COMB_BLOCKS = (int)(((long)BSn*Dn/4 + 255) / 256);

    for (int l = 0; l < Ln; l++) {
        const __half* Wq_l = Wq_h + (long)l*Dn*Dn; const float* bq_l = bq + (long)l*Dn;
        const __half* Wk_l = Wk_h + (long)l*Dn*Dn; const float* bk_l = bk + (long)l*Dn;
        const __half* Wv_l = Wv_h + (long)l*Dn*Dn; const float* bv_l = bv + (long)l*Dn;
        const __half* Wo_l = Wo_h + (long)l*Dn*Dn; const float* bo_l = bo + (long)l*Dn;
        const __half* W1_l = W1_h + (long)l*Dn*Fn; const float* b1_l = b1 + (long)l*Fn;
        const __half* W2_l = W2_h + (long)l*Fn*Dn; const float* b2_l = b2 + (long)l*Dn;
        float* maps = out + (long)BSn*Dn + (long)l*Bn*Hn*Sn*Sn;

        // QKV fused -> head layout (q,k half; v fp32)
        {
            dim3 grid(Dn/128, BSn/128, 3);
            gemm_h<128,128,1,true,false><<<grid,256,SMEM_H128>>>(
                hh, Wq_l, Wk_l, Wv_l, bq_l, bk_l, bv_l,
                (void*)qh, (void*)kh, (void*)v32,
                BSn, Dn, Dn, Dn, Dn, 0, 0,0,0, 0);
        }
        // scores: half single-shot (exp(s/8) to maps + tile sums)
        {
            dim3 grid(Sn/128, Sn/128, BHn);
            scores_kernel<<<grid,256,SMEM_SC>>>(qh, kh, maps, ssum);
        }
        // O = (E @ V) * sc, K-split 2; probs to maps; partials to o[0],o[1]
        {
            dim3 grid(2, Sn/128, BHn);
            av_kernel<<<grid,256,SMEM_AV>>>(maps, v32, o, ssum);
        }
        combine_o<<<COMB_BLOCKS,256>>>(o, o + (long)BSn*Dn, ohh);
        // attn_out partials: t_c = o @ Wo[kc]  (K-split 2; bias folded into LN1)
        {
            dim3 grid(Dn/64, BSn/128, 2);
            gemm_h<128,64,0,false,false><<<grid,256,SMEM_H64>>>(
                ohh, Wo_l, nullptr, nullptr, nullptr, nullptr, nullptr,
                (void*)t, nullptr, nullptr,
                BSn, Dn, Dn/2, Dn, Dn, Dn,
                (long)(Dn/2), (long)(Dn/2)*Dn, (long)BSn*Dn, 0);
        }
        add_ln_kernel<<<BSn,256>>>(h, t, t + (long)BSn*Dn, bo_l,
                                   ln1g + (long)l*Dn, ln1b + (long)l*Dn, h, hh);
        // ff = relu(hh @ W1 + b1) -> half
        {
            dim3 grid(Fn/128, BSn/128, 1);
            gemm_h<128,128,0,false,true><<<grid,256,SMEM_H128>>>(
                hh, W1_l, nullptr, nullptr, b1_l, nullptr, nullptr,
                (void*)ffh, nullptr, nullptr,
                BSn, Fn, Dn, Dn, Fn, Fn, 0,0,0, 1);
        }
        // t_c = ffh @ W2[kc]  (K-split 2; bias folded into LN2)
        {
            dim3 grid(Dn/64, BSn/128, 2);
            gemm_h<128,64,0,false,false><<<grid,256,SMEM_H64>>>(
                ffh, W2_l, nullptr, nullptr, nullptr, nullptr, nullptr,
                (void*)t, nullptr, nullptr,
                BSn, Dn, Fn/2, Fn, Dn, Dn,
                (long)(Fn/2), (long)(Fn/2)*Dn, (long)BSn*Dn, 0);
        }
        if (l == Ln-1)
            add_ln_kernel<<<BSn,256>>>(h, t, t + (long)BSn*Dn, b2_l,
                                       ln2g + (long)l*Dn, ln2b + (long)l*Dn, out, nullptr);
        else
            add_ln_kernel<<<BSn,256>>>(h, t, t + (long)BSn*Dn, b2_l,
                                       ln2g + (long)l*Dn, ln2b + (long)l*Dn, h, hh);
    }
}